// round 3
// baseline (speedup 1.0000x reference)
#include <cuda_runtime.h>
#include <math.h>

#define NN   24576
#define DIN  92
#define DM   512
#define NH   8
#define HD   64
#define NL   3
#define DFF  2048
#define BG   128
#define LN_EPS 1e-5f

// ---------------- scratch (static device globals; no allocs allowed) --------
__device__ float g_h[(size_t)NN * DM];        // 0: running hidden state
__device__ float g_qkv[(size_t)NN * 3 * DM];  // 1: qkv
__device__ float g_tmp[(size_t)NN * DM];      // 2: attn out / ffn2 out
__device__ float g_x[(size_t)NN * DM];        // 3: post-LN1 state
__device__ float g_ffn[(size_t)NN * DFF];     // 4: ffn hidden
__device__ float g_pooled[BG * DM];
__device__ int   g_counts[BG];
__device__ int   g_starts[BG];

#define BUF_H    0
#define BUF_QKV  1
#define BUF_TMP  2
#define BUF_X    3
#define BUF_FFN  4

__device__ __forceinline__ float* buf_ptr(int id) {
    switch (id) {
        case BUF_H:   return g_h;
        case BUF_QKV: return g_qkv;
        case BUF_TMP: return g_tmp;
        case BUF_X:   return g_x;
        default:      return g_ffn;
    }
}

// ---------------- graph bookkeeping (single block, dtype-agnostic) ----------
// Reads batch as int32 words. If the harness kept int64, every odd word in
// the buffer is 0 (values < 128); if it converted to int32, odd words in the
// upper half hold batch values >= ~64. Detect, then count with clamping so
// no atomic can ever leave g_counts.
__global__ __launch_bounds__(256) void k_bookkeep(const int* __restrict__ b32)
{
    __shared__ int s_cnt[BG];
    __shared__ int s_any;
    int tid = threadIdx.x;

    if (tid == 0) s_any = 0;
    for (int i = tid; i < BG; i += 256) s_cnt[i] = 0;
    __syncthreads();

    // detect: scan odd-index words in [NN/2, NN) (safe under both layouts)
    int any = 0;
    for (int i = (NN / 2) + 1 + 2 * tid; i < NN; i += 2 * 256)
        if (b32[i] != 0) any = 1;
    if (any) atomicOr(&s_any, 1);
    __syncthreads();
    int is64 = (s_any == 0);   // all-zero odd words -> int64 layout

    // count (shared atomics), clamped index
    for (int i = tid; i < NN; i += 256) {
        int v = is64 ? b32[2 * i] : b32[i];
        v = min(max(v, 0), BG - 1);
        atomicAdd(&s_cnt[v], 1);
    }
    __syncthreads();

    if (tid == 0) {
        int s = 0;
        for (int i = 0; i < BG; i++) {
            g_counts[i] = s_cnt[i];
            g_starts[i] = s;
            s += s_cnt[i];
        }
    }
}

// ---------------- GEMM: C[M,Nout] = A[M,K] @ W[Nout,K]^T + bias -------------
// 128x128x8 tile, 8x8 microtile, 256 threads.
// aid < 0 -> use external pointer Aext; otherwise scratch buffer id.
template <int ACT>   // 0 = none, 1 = relu
__global__ __launch_bounds__(256) void gemm_kernel(
    const float* __restrict__ Aext, int aid,
    const float* __restrict__ W, const float* __restrict__ bias,
    int cid, int M, int K, int Nout)
{
    __shared__ __align__(16) float As[8][128];
    __shared__ __align__(16) float Ws[8][128];

    const float* A = (aid < 0) ? Aext : buf_ptr(aid);
    float*       C = buf_ptr(cid);

    int tid = threadIdx.x;
    int tx = tid & 15;        // 0..15 -> 8 cols each
    int ty = tid >> 4;        // 0..15 -> 8 rows each
    int m0 = blockIdx.y * 128;
    int n0 = blockIdx.x * 128;

    int lr = tid >> 1;        // 0..127
    int lc = (tid & 1) * 4;   // 0 or 4

    float acc[8][8];
    #pragma unroll
    for (int i = 0; i < 8; i++)
        #pragma unroll
        for (int j = 0; j < 8; j++) acc[i][j] = 0.f;

    int ktiles = (K + 7) / 8;
    const float* Arow = A + (size_t)(m0 + lr) * K;
    const float* Wrow = W + (size_t)(n0 + lr) * K;

    for (int kt = 0; kt < ktiles; kt++) {
        int k0 = kt * 8;
        #pragma unroll
        for (int i = 0; i < 4; i++) {
            int k = lc + i;
            int kg = k0 + k;
            As[k][lr] = (kg < K) ? Arow[kg] : 0.f;
            Ws[k][lr] = (kg < K) ? Wrow[kg] : 0.f;
        }
        __syncthreads();
        #pragma unroll
        for (int k = 0; k < 8; k++) {
            float4 a0 = *(const float4*)(&As[k][ty * 8]);
            float4 a1 = *(const float4*)(&As[k][ty * 8 + 4]);
            float4 b0 = *(const float4*)(&Ws[k][tx * 8]);
            float4 b1 = *(const float4*)(&Ws[k][tx * 8 + 4]);
            float ar[8] = {a0.x, a0.y, a0.z, a0.w, a1.x, a1.y, a1.z, a1.w};
            float br[8] = {b0.x, b0.y, b0.z, b0.w, b1.x, b1.y, b1.z, b1.w};
            #pragma unroll
            for (int i = 0; i < 8; i++)
                #pragma unroll
                for (int j = 0; j < 8; j++)
                    acc[i][j] = fmaf(ar[i], br[j], acc[i][j]);
        }
        __syncthreads();
    }

    #pragma unroll
    for (int i = 0; i < 8; i++) {
        int m = m0 + ty * 8 + i;
        float* Crow = C + (size_t)m * Nout + n0 + tx * 8;
        #pragma unroll
        for (int j = 0; j < 8; j++) {
            float r = acc[i][j] + bias[n0 + tx * 8 + j];
            if (ACT == 1) r = fmaxf(r, 0.f);
            Crow[j] = r;
        }
    }
}

// ---------------- ragged per-graph flash attention --------------------------
// grid (BG, NH, 16 q-tiles of 32), 256 threads. thread = (q = tid>>3, dg = tid&7)
__global__ __launch_bounds__(256) void attn_kernel()
{
    int b  = blockIdx.x;
    int h  = blockIdx.y;
    int qt = blockIdx.z;
    int cnt = g_counts[b];
    int q0  = qt * 32;
    if (q0 >= cnt) return;
    int start = g_starts[b];
    int nq = min(32, cnt - q0);

    __shared__ float Qs[32][65];
    __shared__ float Ks[32][65];
    __shared__ float Vs[32][65];
    __shared__ float Sc[32][33];

    int tid = threadIdx.x;

    for (int idx = tid; idx < 32 * 64; idx += 256) {
        int r = idx >> 6, d = idx & 63;
        Qs[r][d] = (r < nq)
            ? g_qkv[(size_t)(start + q0 + r) * (3 * DM) + h * HD + d] : 0.f;
    }

    int q  = tid >> 3;
    int dg = tid & 7;
    int d0 = dg * 8;

    float acc[8];
    #pragma unroll
    for (int i = 0; i < 8; i++) acc[i] = 0.f;
    float mloc = -INFINITY, lloc = 0.f;
    const float scale = 0.125f;   // 1/sqrt(64)

    for (int k0 = 0; k0 < cnt; k0 += 32) {
        int nk = min(32, cnt - k0);
        __syncthreads();
        for (int idx = tid; idx < 32 * 64; idx += 256) {
            int r = idx >> 6, d = idx & 63;
            if (r < nk) {
                size_t base = (size_t)(start + k0 + r) * (3 * DM) + h * HD + d;
                Ks[r][d] = g_qkv[base + DM];
                Vs[r][d] = g_qkv[base + 2 * DM];
            }
        }
        __syncthreads();

        // scores: this thread computes k = dg*4 .. dg*4+3 for its q row
        float s[4] = {0.f, 0.f, 0.f, 0.f};
        for (int d = 0; d < 64; d++) {
            float qv = Qs[q][d];
            #pragma unroll
            for (int kk = 0; kk < 4; kk++)
                s[kk] = fmaf(qv, Ks[dg * 4 + kk][d], s[kk]);
        }
        #pragma unroll
        for (int kk = 0; kk < 4; kk++) {
            int k = dg * 4 + kk;
            Sc[q][k] = (k < nk) ? s[kk] * scale : -INFINITY;
        }
        __syncthreads();

        // online softmax update
        float mc = -INFINITY;
        #pragma unroll
        for (int k = 0; k < 32; k++) mc = fmaxf(mc, Sc[q][k]);
        float mnew = fmaxf(mloc, mc);
        float corr = (mloc == -INFINITY) ? 0.f : __expf(mloc - mnew);
        lloc *= corr;
        #pragma unroll
        for (int i = 0; i < 8; i++) acc[i] *= corr;
        for (int k = 0; k < nk; k++) {
            float p = __expf(Sc[q][k] - mnew);
            lloc += p;
            #pragma unroll
            for (int i = 0; i < 8; i++)
                acc[i] = fmaf(p, Vs[k][d0 + i], acc[i]);
        }
        mloc = mnew;
        __syncthreads();
    }

    if (q < nq) {
        float inv = 1.f / lloc;
        size_t base = (size_t)(start + q0 + q) * DM + h * HD + d0;
        #pragma unroll
        for (int i = 0; i < 8; i++) g_tmp[base + i] = acc[i] * inv;
    }
}

// ---------------- residual + layernorm --------------------------------------
__global__ __launch_bounds__(128) void ln_kernel(
    int rid, int did, int oid,
    const float* __restrict__ gg, const float* __restrict__ bb)
{
    const float* resid = buf_ptr(rid);
    const float* delta = buf_ptr(did);
    float*       out   = buf_ptr(oid);

    int row = blockIdx.x;
    int tid = threadIdx.x;
    size_t base = (size_t)row * DM;

    float v[4];
    float s = 0.f, sq = 0.f;
    #pragma unroll
    for (int i = 0; i < 4; i++) {
        int c = tid + i * 128;
        float x = resid[base + c] + delta[base + c];
        v[i] = x;
        s += x; sq += x * x;
    }
    __shared__ float shs[4], shq[4];
    #pragma unroll
    for (int o = 16; o > 0; o >>= 1) {
        s  += __shfl_down_sync(0xffffffffu, s, o);
        sq += __shfl_down_sync(0xffffffffu, sq, o);
    }
    int w = tid >> 5;
    if ((tid & 31) == 0) { shs[w] = s; shq[w] = sq; }
    __syncthreads();
    float ts = shs[0] + shs[1] + shs[2] + shs[3];
    float tq = shq[0] + shq[1] + shq[2] + shq[3];
    float mean = ts * (1.f / DM);
    float var  = tq * (1.f / DM) - mean * mean;
    float inv  = rsqrtf(fmaxf(var, 0.f) + LN_EPS);
    #pragma unroll
    for (int i = 0; i < 4; i++) {
        int c = tid + i * 128;
        out[base + c] = (v[i] - mean) * inv * gg[c] + bb[c];
    }
}

// ---------------- segment mean pool -----------------------------------------
__global__ __launch_bounds__(256) void pool_kernel()
{
    int b = blockIdx.x;
    int tid = threadIdx.x;
    int cnt = g_counts[b], st = g_starts[b];
    float a0 = 0.f, a1 = 0.f;
    for (int r = 0; r < cnt; r++) {
        size_t base = (size_t)(st + r) * DM;
        a0 += g_h[base + tid];
        a1 += g_h[base + tid + 256];
    }
    float inv = (cnt > 0) ? 1.f / (float)cnt : 0.f;
    g_pooled[b * DM + tid]       = a0 * inv;
    g_pooled[b * DM + tid + 256] = a1 * inv;
}

// ---------------- head: silu(pooled @ w1^T + b1) @ w2^T + b2 ----------------
__global__ __launch_bounds__(256) void head_kernel(
    const float* __restrict__ w1, const float* __restrict__ b1,
    const float* __restrict__ w2, const float* __restrict__ b2,
    float* __restrict__ out)
{
    int b = blockIdx.x;
    int tid = threadIdx.x;
    __shared__ float ps[DM];
    ps[tid]       = g_pooled[b * DM + tid];
    ps[tid + 256] = g_pooled[b * DM + tid + 256];
    __syncthreads();

    int warp = tid >> 5, lane = tid & 31;
    float partial = 0.f;
    for (int j = warp; j < DM; j += 8) {
        float a = 0.f;
        const float* wr = w1 + (size_t)j * DM;
        for (int k = lane; k < DM; k += 32) a = fmaf(ps[k], wr[k], a);
        #pragma unroll
        for (int o = 16; o > 0; o >>= 1) a += __shfl_down_sync(0xffffffffu, a, o);
        if (lane == 0) {
            a += b1[j];
            float sil = a / (1.f + __expf(-a));
            partial = fmaf(sil, w2[j], partial);
        }
    }
    __shared__ float red[8];
    if (lane == 0) red[warp] = partial;
    __syncthreads();
    if (tid == 0) {
        float t = 0.f;
        #pragma unroll
        for (int i = 0; i < 8; i++) t += red[i];
        out[b] = t + b2[0];
    }
}

// ---------------- launch -----------------------------------------------------
extern "C" void kernel_launch(void* const* d_in, const int* in_sizes, int n_in,
                              void* d_out, int out_size)
{
    const float* node_features = (const float*)d_in[0];
    const int*   batch32       = (const int*)d_in[3];
    const float* emb_w    = (const float*)d_in[4];
    const float* emb_b    = (const float*)d_in[5];
    const float* in_proj_w = (const float*)d_in[6];
    const float* in_proj_b = (const float*)d_in[7];
    const float* out_w    = (const float*)d_in[8];
    const float* out_b    = (const float*)d_in[9];
    const float* ln1_g    = (const float*)d_in[10];
    const float* ln1_b    = (const float*)d_in[11];
    const float* ffn_w1   = (const float*)d_in[12];
    const float* ffn_b1   = (const float*)d_in[13];
    const float* ffn_w2   = (const float*)d_in[14];
    const float* ffn_b2   = (const float*)d_in[15];
    const float* ln2_g    = (const float*)d_in[16];
    const float* ln2_b    = (const float*)d_in[17];
    const float* head_w1  = (const float*)d_in[18];
    const float* head_b1  = (const float*)d_in[19];
    const float* head_w2  = (const float*)d_in[20];
    const float* head_b2  = (const float*)d_in[21];
    float* out = (float*)d_out;

    // graph bookkeeping (dtype-agnostic, clamped)
    k_bookkeep<<<1, 256>>>(batch32);

    // embedding: h = node_features @ emb_w^T + emb_b   (24576 x 92 -> 512)
    gemm_kernel<0><<<dim3(DM / 128, NN / 128), 256>>>(
        node_features, -1, emb_w, emb_b, BUF_H, NN, DIN, DM);

    for (int l = 0; l < NL; l++) {
        const float* ipw = in_proj_w + (size_t)l * 3 * DM * DM;
        const float* ipb = in_proj_b + (size_t)l * 3 * DM;
        const float* ow  = out_w + (size_t)l * DM * DM;
        const float* ob  = out_b + (size_t)l * DM;
        const float* f1w = ffn_w1 + (size_t)l * DFF * DM;
        const float* f1b = ffn_b1 + (size_t)l * DFF;
        const float* f2w = ffn_w2 + (size_t)l * DM * DFF;
        const float* f2b = ffn_b2 + (size_t)l * DM;

        // qkv = h @ ipw^T + ipb          (24576 x 512 -> 1536)
        gemm_kernel<0><<<dim3(3 * DM / 128, NN / 128), 256>>>(
            nullptr, BUF_H, ipw, ipb, BUF_QKV, NN, DM, 3 * DM);

        // per-graph attention -> g_tmp
        attn_kernel<<<dim3(BG, NH, 16), 256>>>();

        // o proj -> g_x                  (24576 x 512 -> 512)
        gemm_kernel<0><<<dim3(DM / 128, NN / 128), 256>>>(
            nullptr, BUF_TMP, ow, ob, BUF_X, NN, DM, DM);

        // x = LN(h + o)  (in place into g_x)
        ln_kernel<<<NN, 128>>>(BUF_H, BUF_X, BUF_X,
                               ln1_g + (size_t)l * DM, ln1_b + (size_t)l * DM);

        // ffn1 (relu)                    (24576 x 512 -> 2048)
        gemm_kernel<1><<<dim3(DFF / 128, NN / 128), 256>>>(
            nullptr, BUF_X, f1w, f1b, BUF_FFN, NN, DM, DFF);

        // ffn2 -> g_tmp                  (24576 x 2048 -> 512)
        gemm_kernel<0><<<dim3(DM / 128, NN / 128), 256>>>(
            nullptr, BUF_FFN, f2w, f2b, BUF_TMP, NN, DFF, DM);

        // h = LN(x + f2)
        ln_kernel<<<NN, 128>>>(BUF_X, BUF_TMP, BUF_H,
                               ln2_g + (size_t)l * DM, ln2_b + (size_t)l * DM);
    }

    // pooling + head
    pool_kernel<<<BG, 256>>>();
    head_kernel<<<BG, 256>>>(head_w1, head_b1, head_w2, head_b2, out);
}

// round 4
// speedup vs baseline: 2.4768x; 2.4768x over previous
#include <cuda_runtime.h>
#include <math.h>

#define NN   24576
#define DIN  92
#define DM   512
#define NH   8
#define HD   64
#define NL   3
#define DFF  2048
#define BG   128
#define LN_EPS 1e-5f

// ---------------- scratch (static device globals; no allocs allowed) --------
__device__ float g_h[(size_t)NN * DM];        // 0: running hidden state
__device__ float g_qkv[(size_t)NN * 3 * DM];  // 1: qkv
__device__ float g_tmp[(size_t)NN * DM];      // 2: attn out / ffn2 out
__device__ float g_x[(size_t)NN * DM];        // 3: post-LN1 state
__device__ float g_ffn[(size_t)NN * DFF];     // 4: ffn hidden
__device__ float g_pooled[BG * DM];
__device__ int   g_counts[BG];
__device__ int   g_starts[BG];

#define BUF_H    0
#define BUF_QKV  1
#define BUF_TMP  2
#define BUF_X    3
#define BUF_FFN  4

__device__ __forceinline__ float* buf_ptr(int id) {
    switch (id) {
        case BUF_H:   return g_h;
        case BUF_QKV: return g_qkv;
        case BUF_TMP: return g_tmp;
        case BUF_X:   return g_x;
        default:      return g_ffn;
    }
}

// ---------------- graph bookkeeping (single block, dtype-agnostic) ----------
__global__ __launch_bounds__(256) void k_bookkeep(const int* __restrict__ b32)
{
    __shared__ int s_cnt[BG];
    __shared__ int s_any;
    int tid = threadIdx.x;

    if (tid == 0) s_any = 0;
    for (int i = tid; i < BG; i += 256) s_cnt[i] = 0;
    __syncthreads();

    // detect int64 vs int32 layout: odd words all zero -> int64
    int any = 0;
    for (int i = (NN / 2) + 1 + 2 * tid; i < NN; i += 2 * 256)
        if (b32[i] != 0) any = 1;
    if (any) atomicOr(&s_any, 1);
    __syncthreads();
    int is64 = (s_any == 0);

    for (int i = tid; i < NN; i += 256) {
        int v = is64 ? b32[2 * i] : b32[i];
        v = min(max(v, 0), BG - 1);
        atomicAdd(&s_cnt[v], 1);
    }
    __syncthreads();

    if (tid == 0) {
        int s = 0;
        for (int i = 0; i < BG; i++) {
            g_counts[i] = s_cnt[i];
            g_starts[i] = s;
            s += s_cnt[i];
        }
    }
}

// ---------------- GEMM: C[M,Nout] = A[M,K] @ W[Nout,K]^T + bias -------------
// 128x128x16 tile, 8x8 microtile, 256 threads, double-buffered smem,
// coalesced float4 global loads with transposed smem store.
template <int ACT>   // 0 = none, 1 = relu
__global__ __launch_bounds__(256) void gemm_kernel(
    const float* __restrict__ Aext, int aid,
    const float* __restrict__ W, const float* __restrict__ bias,
    int cid, int M, int K, int Nout)
{
    __shared__ __align__(16) float As[2][16][132];
    __shared__ __align__(16) float Ws[2][16][132];

    const float* A = (aid < 0) ? Aext : buf_ptr(aid);
    float*       C = buf_ptr(cid);

    const int tid = threadIdx.x;
    const int tx = tid & 15;          // 0..15 -> 8 output cols each
    const int ty = tid >> 4;          // 0..15 -> 8 output rows each
    const int m0 = blockIdx.y * 128;
    const int n0 = blockIdx.x * 128;

    const int lr = tid >> 2;          // 0..63 loader row
    const int lc = (tid & 3) * 4;     // 0,4,8,12 loader col group

    const float* Ap0 = A + (size_t)(m0 + lr) * K;
    const float* Ap1 = A + (size_t)(m0 + lr + 64) * K;
    const float* Wp0 = W + (size_t)(n0 + lr) * K;
    const float* Wp1 = W + (size_t)(n0 + lr + 64) * K;

    float acc[8][8];
    #pragma unroll
    for (int i = 0; i < 8; i++)
        #pragma unroll
        for (int j = 0; j < 8; j++) acc[i][j] = 0.f;

    float4 ra0, ra1, rw0, rw1;

    const int ktiles = (K + 15) >> 4;

#define GLOAD(k0)                                                            \
    do {                                                                     \
        if ((k0) + 16 <= K) {                                                \
            ra0 = *(const float4*)(Ap0 + (k0) + lc);                         \
            ra1 = *(const float4*)(Ap1 + (k0) + lc);                         \
            rw0 = *(const float4*)(Wp0 + (k0) + lc);                         \
            rw1 = *(const float4*)(Wp1 + (k0) + lc);                         \
        } else {                                                             \
            float* p0 = (float*)&ra0; float* p1 = (float*)&ra1;              \
            float* q0 = (float*)&rw0; float* q1 = (float*)&rw1;              \
            _Pragma("unroll")                                                \
            for (int i = 0; i < 4; i++) {                                    \
                int kg = (k0) + lc + i;                                      \
                bool ok = (kg < K);                                          \
                p0[i] = ok ? Ap0[kg] : 0.f;                                  \
                p1[i] = ok ? Ap1[kg] : 0.f;                                  \
                q0[i] = ok ? Wp0[kg] : 0.f;                                  \
                q1[i] = ok ? Wp1[kg] : 0.f;                                  \
            }                                                                \
        }                                                                    \
    } while (0)

#define SSTORE(bf)                                                           \
    do {                                                                     \
        As[bf][lc + 0][lr]      = ra0.x;                                     \
        As[bf][lc + 1][lr]      = ra0.y;                                     \
        As[bf][lc + 2][lr]      = ra0.z;                                     \
        As[bf][lc + 3][lr]      = ra0.w;                                     \
        As[bf][lc + 0][lr + 64] = ra1.x;                                     \
        As[bf][lc + 1][lr + 64] = ra1.y;                                     \
        As[bf][lc + 2][lr + 64] = ra1.z;                                     \
        As[bf][lc + 3][lr + 64] = ra1.w;                                     \
        Ws[bf][lc + 0][lr]      = rw0.x;                                     \
        Ws[bf][lc + 1][lr]      = rw0.y;                                     \
        Ws[bf][lc + 2][lr]      = rw0.z;                                     \
        Ws[bf][lc + 3][lr]      = rw0.w;                                     \
        Ws[bf][lc + 0][lr + 64] = rw1.x;                                     \
        Ws[bf][lc + 1][lr + 64] = rw1.y;                                     \
        Ws[bf][lc + 2][lr + 64] = rw1.z;                                     \
        Ws[bf][lc + 3][lr + 64] = rw1.w;                                     \
    } while (0)

#define COMPUTE(bf)                                                          \
    do {                                                                     \
        _Pragma("unroll")                                                    \
        for (int k = 0; k < 16; k++) {                                       \
            float4 a0 = *(const float4*)(&As[bf][k][ty * 8]);                \
            float4 a1 = *(const float4*)(&As[bf][k][ty * 8 + 4]);            \
            float4 b0 = *(const float4*)(&Ws[bf][k][tx * 8]);                \
            float4 b1 = *(const float4*)(&Ws[bf][k][tx * 8 + 4]);            \
            float ar[8] = {a0.x, a0.y, a0.z, a0.w, a1.x, a1.y, a1.z, a1.w};  \
            float br[8] = {b0.x, b0.y, b0.z, b0.w, b1.x, b1.y, b1.z, b1.w};  \
            _Pragma("unroll")                                                \
            for (int i = 0; i < 8; i++)                                      \
                _Pragma("unroll")                                            \
                for (int j = 0; j < 8; j++)                                  \
                    acc[i][j] = fmaf(ar[i], br[j], acc[i][j]);               \
        }                                                                    \
    } while (0)

    GLOAD(0);
    SSTORE(0);
    __syncthreads();

    for (int kt = 0; kt < ktiles; kt++) {
        int bf = kt & 1;
        if (kt + 1 < ktiles) GLOAD((kt + 1) * 16);
        COMPUTE(bf);
        if (kt + 1 < ktiles) {
            SSTORE(bf ^ 1);
            __syncthreads();
        }
    }

#undef GLOAD
#undef SSTORE
#undef COMPUTE

    // epilogue
    float4 bia0 = *(const float4*)(bias + n0 + tx * 8);
    float4 bia1 = *(const float4*)(bias + n0 + tx * 8 + 4);
    float bb[8] = {bia0.x, bia0.y, bia0.z, bia0.w, bia1.x, bia1.y, bia1.z, bia1.w};

    #pragma unroll
    for (int i = 0; i < 8; i++) {
        int m = m0 + ty * 8 + i;
        float* Crow = C + (size_t)m * Nout + n0 + tx * 8;
        float4 o0, o1;
        float r[8];
        #pragma unroll
        for (int j = 0; j < 8; j++) {
            r[j] = acc[i][j] + bb[j];
            if (ACT == 1) r[j] = fmaxf(r[j], 0.f);
        }
        o0.x = r[0]; o0.y = r[1]; o0.z = r[2]; o0.w = r[3];
        o1.x = r[4]; o1.y = r[5]; o1.z = r[6]; o1.w = r[7];
        *(float4*)(Crow)     = o0;
        *(float4*)(Crow + 4) = o1;
    }
}

// ---------------- ragged per-graph flash attention --------------------------
// grid (BG, NH, 16 q-tiles of 32), 256 threads. thread = (q = tid>>3, dg = tid&7)
__global__ __launch_bounds__(256) void attn_kernel()
{
    int b  = blockIdx.x;
    int h  = blockIdx.y;
    int qt = blockIdx.z;
    int cnt = g_counts[b];
    int q0  = qt * 32;
    if (q0 >= cnt) return;
    int start = g_starts[b];
    int nq = min(32, cnt - q0);

    __shared__ float Qs[32][65];
    __shared__ float Ks[32][65];
    __shared__ float Vs[32][65];
    __shared__ float Sc[32][33];

    int tid = threadIdx.x;

    for (int idx = tid; idx < 32 * 64; idx += 256) {
        int r = idx >> 6, d = idx & 63;
        Qs[r][d] = (r < nq)
            ? g_qkv[(size_t)(start + q0 + r) * (3 * DM) + h * HD + d] : 0.f;
    }

    int q  = tid >> 3;
    int dg = tid & 7;
    int d0 = dg * 8;

    float acc[8];
    #pragma unroll
    for (int i = 0; i < 8; i++) acc[i] = 0.f;
    float mloc = -INFINITY, lloc = 0.f;
    const float scale = 0.125f;   // 1/sqrt(64)

    for (int k0 = 0; k0 < cnt; k0 += 32) {
        int nk = min(32, cnt - k0);
        __syncthreads();
        for (int idx = tid; idx < 32 * 64; idx += 256) {
            int r = idx >> 6, d = idx & 63;
            if (r < nk) {
                size_t base = (size_t)(start + k0 + r) * (3 * DM) + h * HD + d;
                Ks[r][d] = g_qkv[base + DM];
                Vs[r][d] = g_qkv[base + 2 * DM];
            }
        }
        __syncthreads();

        float s[4] = {0.f, 0.f, 0.f, 0.f};
        for (int d = 0; d < 64; d++) {
            float qv = Qs[q][d];
            #pragma unroll
            for (int kk = 0; kk < 4; kk++)
                s[kk] = fmaf(qv, Ks[dg * 4 + kk][d], s[kk]);
        }
        #pragma unroll
        for (int kk = 0; kk < 4; kk++) {
            int k = dg * 4 + kk;
            Sc[q][k] = (k < nk) ? s[kk] * scale : -INFINITY;
        }
        __syncthreads();

        float mc = -INFINITY;
        #pragma unroll
        for (int k = 0; k < 32; k++) mc = fmaxf(mc, Sc[q][k]);
        float mnew = fmaxf(mloc, mc);
        float corr = (mloc == -INFINITY) ? 0.f : __expf(mloc - mnew);
        lloc *= corr;
        #pragma unroll
        for (int i = 0; i < 8; i++) acc[i] *= corr;
        for (int k = 0; k < nk; k++) {
            float p = __expf(Sc[q][k] - mnew);
            lloc += p;
            #pragma unroll
            for (int i = 0; i < 8; i++)
                acc[i] = fmaf(p, Vs[k][d0 + i], acc[i]);
        }
        mloc = mnew;
        __syncthreads();
    }

    if (q < nq) {
        float inv = 1.f / lloc;
        size_t base = (size_t)(start + q0 + q) * DM + h * HD + d0;
        #pragma unroll
        for (int i = 0; i < 8; i++) g_tmp[base + i] = acc[i] * inv;
    }
}

// ---------------- residual + layernorm --------------------------------------
__global__ __launch_bounds__(128) void ln_kernel(
    int rid, int did, int oid,
    const float* __restrict__ gg, const float* __restrict__ bb)
{
    const float* resid = buf_ptr(rid);
    const float* delta = buf_ptr(did);
    float*       out   = buf_ptr(oid);

    int row = blockIdx.x;
    int tid = threadIdx.x;
    size_t base = (size_t)row * DM;

    float v[4];
    float s = 0.f, sq = 0.f;
    #pragma unroll
    for (int i = 0; i < 4; i++) {
        int c = tid + i * 128;
        float x = resid[base + c] + delta[base + c];
        v[i] = x;
        s += x; sq += x * x;
    }
    __shared__ float shs[4], shq[4];
    #pragma unroll
    for (int o = 16; o > 0; o >>= 1) {
        s  += __shfl_down_sync(0xffffffffu, s, o);
        sq += __shfl_down_sync(0xffffffffu, sq, o);
    }
    int w = tid >> 5;
    if ((tid & 31) == 0) { shs[w] = s; shq[w] = sq; }
    __syncthreads();
    float ts = shs[0] + shs[1] + shs[2] + shs[3];
    float tq = shq[0] + shq[1] + shq[2] + shq[3];
    float mean = ts * (1.f / DM);
    float var  = tq * (1.f / DM) - mean * mean;
    float inv  = rsqrtf(fmaxf(var, 0.f) + LN_EPS);
    #pragma unroll
    for (int i = 0; i < 4; i++) {
        int c = tid + i * 128;
        out[base + c] = (v[i] - mean) * inv * gg[c] + bb[c];
    }
}

// ---------------- segment mean pool -----------------------------------------
__global__ __launch_bounds__(256) void pool_kernel()
{
    int b = blockIdx.x;
    int tid = threadIdx.x;
    int cnt = g_counts[b], st = g_starts[b];
    float a0 = 0.f, a1 = 0.f;
    for (int r = 0; r < cnt; r++) {
        size_t base = (size_t)(st + r) * DM;
        a0 += g_h[base + tid];
        a1 += g_h[base + tid + 256];
    }
    float inv = (cnt > 0) ? 1.f / (float)cnt : 0.f;
    g_pooled[b * DM + tid]       = a0 * inv;
    g_pooled[b * DM + tid + 256] = a1 * inv;
}

// ---------------- head: silu(pooled @ w1^T + b1) @ w2^T + b2 ----------------
__global__ __launch_bounds__(256) void head_kernel(
    const float* __restrict__ w1, const float* __restrict__ b1,
    const float* __restrict__ w2, const float* __restrict__ b2,
    float* __restrict__ out)
{
    int b = blockIdx.x;
    int tid = threadIdx.x;
    __shared__ float ps[DM];
    ps[tid]       = g_pooled[b * DM + tid];
    ps[tid + 256] = g_pooled[b * DM + tid + 256];
    __syncthreads();

    int warp = tid >> 5, lane = tid & 31;
    float partial = 0.f;
    for (int j = warp; j < DM; j += 8) {
        float a = 0.f;
        const float* wr = w1 + (size_t)j * DM;
        for (int k = lane; k < DM; k += 32) a = fmaf(ps[k], wr[k], a);
        #pragma unroll
        for (int o = 16; o > 0; o >>= 1) a += __shfl_down_sync(0xffffffffu, a, o);
        if (lane == 0) {
            a += b1[j];
            float sil = a / (1.f + __expf(-a));
            partial = fmaf(sil, w2[j], partial);
        }
    }
    __shared__ float red[8];
    if (lane == 0) red[warp] = partial;
    __syncthreads();
    if (tid == 0) {
        float t = 0.f;
        #pragma unroll
        for (int i = 0; i < 8; i++) t += red[i];
        out[b] = t + b2[0];
    }
}

// ---------------- launch -----------------------------------------------------
extern "C" void kernel_launch(void* const* d_in, const int* in_sizes, int n_in,
                              void* d_out, int out_size)
{
    const float* node_features = (const float*)d_in[0];
    const int*   batch32       = (const int*)d_in[3];
    const float* emb_w    = (const float*)d_in[4];
    const float* emb_b    = (const float*)d_in[5];
    const float* in_proj_w = (const float*)d_in[6];
    const float* in_proj_b = (const float*)d_in[7];
    const float* out_w    = (const float*)d_in[8];
    const float* out_b    = (const float*)d_in[9];
    const float* ln1_g    = (const float*)d_in[10];
    const float* ln1_b    = (const float*)d_in[11];
    const float* ffn_w1   = (const float*)d_in[12];
    const float* ffn_b1   = (const float*)d_in[13];
    const float* ffn_w2   = (const float*)d_in[14];
    const float* ffn_b2   = (const float*)d_in[15];
    const float* ln2_g    = (const float*)d_in[16];
    const float* ln2_b    = (const float*)d_in[17];
    const float* head_w1  = (const float*)d_in[18];
    const float* head_b1  = (const float*)d_in[19];
    const float* head_w2  = (const float*)d_in[20];
    const float* head_b2  = (const float*)d_in[21];
    float* out = (float*)d_out;

    // graph bookkeeping (dtype-agnostic, clamped)
    k_bookkeep<<<1, 256>>>(batch32);

    // embedding: h = node_features @ emb_w^T + emb_b   (24576 x 92 -> 512)
    gemm_kernel<0><<<dim3(DM / 128, NN / 128), 256>>>(
        node_features, -1, emb_w, emb_b, BUF_H, NN, DIN, DM);

    for (int l = 0; l < NL; l++) {
        const float* ipw = in_proj_w + (size_t)l * 3 * DM * DM;
        const float* ipb = in_proj_b + (size_t)l * 3 * DM;
        const float* ow  = out_w + (size_t)l * DM * DM;
        const float* ob  = out_b + (size_t)l * DM;
        const float* f1w = ffn_w1 + (size_t)l * DFF * DM;
        const float* f1b = ffn_b1 + (size_t)l * DFF;
        const float* f2w = ffn_w2 + (size_t)l * DM * DFF;
        const float* f2b = ffn_b2 + (size_t)l * DM;

        // qkv = h @ ipw^T + ipb          (24576 x 512 -> 1536)
        gemm_kernel<0><<<dim3(3 * DM / 128, NN / 128), 256>>>(
            nullptr, BUF_H, ipw, ipb, BUF_QKV, NN, DM, 3 * DM);

        // per-graph attention -> g_tmp
        attn_kernel<<<dim3(BG, NH, 16), 256>>>();

        // o proj -> g_x                  (24576 x 512 -> 512)
        gemm_kernel<0><<<dim3(DM / 128, NN / 128), 256>>>(
            nullptr, BUF_TMP, ow, ob, BUF_X, NN, DM, DM);

        // x = LN(h + o)  (in place into g_x)
        ln_kernel<<<NN, 128>>>(BUF_H, BUF_X, BUF_X,
                               ln1_g + (size_t)l * DM, ln1_b + (size_t)l * DM);

        // ffn1 (relu)                    (24576 x 512 -> 2048)
        gemm_kernel<1><<<dim3(DFF / 128, NN / 128), 256>>>(
            nullptr, BUF_X, f1w, f1b, BUF_FFN, NN, DM, DFF);

        // ffn2 -> g_tmp                  (24576 x 2048 -> 512)
        gemm_kernel<0><<<dim3(DM / 128, NN / 128), 256>>>(
            nullptr, BUF_FFN, f2w, f2b, BUF_TMP, NN, DFF, DM);

        // h = LN(x + f2)
        ln_kernel<<<NN, 128>>>(BUF_X, BUF_TMP, BUF_H,
                               ln2_g + (size_t)l * DM, ln2_b + (size_t)l * DM);
    }

    // pooling + head
    pool_kernel<<<BG, 256>>>();
    head_kernel<<<BG, 256>>>(head_w1, head_b1, head_w2, head_b2, out);
}

// round 8
// speedup vs baseline: 2.5775x; 1.0406x over previous
#include <cuda_runtime.h>
#include <math.h>
#include <stdint.h>

#define NN   24576
#define DIN  92
#define DM   512
#define NH   8
#define HD   64
#define NL   3
#define DFF  2048
#define BG   128
#define LN_EPS 1e-5f

// ---------------- scratch (static device globals; no allocs allowed) --------
__device__ float g_h[(size_t)NN * DM];
__device__ float g_qkv[(size_t)NN * 3 * DM];
__device__ float g_tmp[(size_t)NN * DM];
__device__ float g_x[(size_t)NN * DM];
__device__ float g_ffn[(size_t)NN * DFF];
__device__ float g_pooled[BG * DM];
__device__ int   g_counts[BG];
__device__ int   g_starts[BG];

#define BUF_H    0
#define BUF_QKV  1
#define BUF_TMP  2
#define BUF_X    3
#define BUF_FFN  4

__device__ __forceinline__ float* buf_ptr(int id) {
    switch (id) {
        case BUF_H:   return g_h;
        case BUF_QKV: return g_qkv;
        case BUF_TMP: return g_tmp;
        case BUF_X:   return g_x;
        default:      return g_ffn;
    }
}

// ---------------- graph bookkeeping -----------------------------------------
__global__ __launch_bounds__(256) void k_bookkeep(const int* __restrict__ b32)
{
    __shared__ int s_cnt[BG];
    __shared__ int s_any;
    int tid = threadIdx.x;

    if (tid == 0) s_any = 0;
    for (int i = tid; i < BG; i += 256) s_cnt[i] = 0;
    __syncthreads();

    int any = 0;
    for (int i = (NN / 2) + 1 + 2 * tid; i < NN; i += 2 * 256)
        if (b32[i] != 0) any = 1;
    if (any) atomicOr(&s_any, 1);
    __syncthreads();
    int is64 = (s_any == 0);

    for (int i = tid; i < NN; i += 256) {
        int v = is64 ? b32[2 * i] : b32[i];
        v = min(max(v, 0), BG - 1);
        atomicAdd(&s_cnt[v], 1);
    }
    __syncthreads();

    if (tid == 0) {
        int s = 0;
        for (int i = 0; i < BG; i++) {
            g_counts[i] = s_cnt[i];
            g_starts[i] = s;
            s += s_cnt[i];
        }
    }
}

// ---------------- tf32 warp-MMA helpers --------------------------------------
__device__ __forceinline__ uint32_t f2tf32(float f) {
    uint32_t r;
    asm("cvt.rna.tf32.f32 %0, %1;" : "=r"(r) : "f"(f));
    return r;
}

__device__ __forceinline__ void mma_tf32(float* c, const uint32_t* a, const uint32_t* b) {
    asm volatile(
        "mma.sync.aligned.m16n8k8.row.col.f32.tf32.tf32.f32 "
        "{%0,%1,%2,%3}, {%4,%5,%6,%7}, {%8,%9}, {%0,%1,%2,%3};"
        : "+f"(c[0]), "+f"(c[1]), "+f"(c[2]), "+f"(c[3])
        : "r"(a[0]), "r"(a[1]), "r"(a[2]), "r"(a[3]), "r"(b[0]), "r"(b[1]));
}

// ---------------- tensor GEMM: C[M,Nout] = A[M,K] @ W[Nout,K]^T + bias ------
// 128x128 tile, BK=16, double-buffered, 256 threads (8 warps, 4x2),
// warp tile 32x64 via m16n8k8 tf32 mma.sync. K must be a multiple of 16.
#define LDP 132                    // padded row stride (words)
#define GEMM_SMEM (2 * 2 * 16 * LDP * 4)   // 67584 bytes

__global__ void __launch_bounds__(256, 2) gemm_tc(
    int aid, const float* __restrict__ W, const float* __restrict__ bias,
    int cid, int M, int K, int Nout, int act)
{
    extern __shared__ uint32_t dsm[];
    uint32_t* Asm = dsm;                 // [2][16][LDP]
    uint32_t* Wsm = dsm + 2 * 16 * LDP;  // [2][16][LDP]

    const float* A = buf_ptr(aid);
    float*       C = buf_ptr(cid);

    const int tid  = threadIdx.x;
    const int warp = tid >> 5;
    const int lane = tid & 31;
    const int g    = lane >> 2;      // 0..7
    const int tig  = lane & 3;       // 0..3
    const int wm   = (warp >> 1) * 32;   // warp row offset in tile
    const int wn   = (warp & 1) * 64;    // warp col offset in tile

    const int m0 = blockIdx.y * 128;
    const int n0 = blockIdx.x * 128;

    const int lr = tid >> 2;         // 0..63 loader row
    const int lc = (tid & 3) * 4;    // 0,4,8,12 loader k group

    const float* Ap0 = A + (size_t)(m0 + lr) * K;
    const float* Ap1 = A + (size_t)(m0 + lr + 64) * K;
    const float* Wp0 = W + (size_t)(n0 + lr) * K;
    const float* Wp1 = W + (size_t)(n0 + lr + 64) * K;

    float acc[2][8][4];
    #pragma unroll
    for (int i = 0; i < 2; i++)
        #pragma unroll
        for (int j = 0; j < 8; j++)
            #pragma unroll
            for (int r = 0; r < 4; r++) acc[i][j][r] = 0.f;

    float4 ra0, ra1, rw0, rw1;
    const int S = K >> 4;

#define GLOAD(k0)                                              \
    do {                                                       \
        ra0 = *(const float4*)(Ap0 + (k0) + lc);               \
        ra1 = *(const float4*)(Ap1 + (k0) + lc);               \
        rw0 = *(const float4*)(Wp0 + (k0) + lc);               \
        rw1 = *(const float4*)(Wp1 + (k0) + lc);               \
    } while (0)

#define SSTORE(bf)                                                             \
    do {                                                                       \
        uint32_t* Ab = Asm + (bf) * 16 * LDP;                                  \
        uint32_t* Wb = Wsm + (bf) * 16 * LDP;                                  \
        Ab[(lc + 0) * LDP + lr]      = f2tf32(ra0.x);                          \
        Ab[(lc + 1) * LDP + lr]      = f2tf32(ra0.y);                          \
        Ab[(lc + 2) * LDP + lr]      = f2tf32(ra0.z);                          \
        Ab[(lc + 3) * LDP + lr]      = f2tf32(ra0.w);                          \
        Ab[(lc + 0) * LDP + lr + 64] = f2tf32(ra1.x);                          \
        Ab[(lc + 1) * LDP + lr + 64] = f2tf32(ra1.y);                          \
        Ab[(lc + 2) * LDP + lr + 64] = f2tf32(ra1.z);                          \
        Ab[(lc + 3) * LDP + lr + 64] = f2tf32(ra1.w);                          \
        Wb[(lc + 0) * LDP + lr]      = f2tf32(rw0.x);                          \
        Wb[(lc + 1) * LDP + lr]      = f2tf32(rw0.y);                          \
        Wb[(lc + 2) * LDP + lr]      = f2tf32(rw0.z);                          \
        Wb[(lc + 3) * LDP + lr]      = f2tf32(rw0.w);                          \
        Wb[(lc + 0) * LDP + lr + 64] = f2tf32(rw1.x);                          \
        Wb[(lc + 1) * LDP + lr + 64] = f2tf32(rw1.y);                          \
        Wb[(lc + 2) * LDP + lr + 64] = f2tf32(rw1.z);                          \
        Wb[(lc + 3) * LDP + lr + 64] = f2tf32(rw1.w);                          \
    } while (0)

#define COMPUTE(bf)                                                            \
    do {                                                                       \
        const uint32_t* Ab = Asm + (bf) * 16 * LDP;                            \
        const uint32_t* Wb = Wsm + (bf) * 16 * LDP;                            \
        _Pragma("unroll")                                                      \
        for (int kk = 0; kk < 2; kk++) {                                       \
            const int k = kk * 8;                                              \
            uint32_t af[2][4], bf_[8][2];                                      \
            _Pragma("unroll")                                                  \
            for (int i = 0; i < 2; i++) {                                      \
                int rb = wm + i * 16 + g;                                      \
                af[i][0] = Ab[(k + tig) * LDP + rb];                           \
                af[i][1] = Ab[(k + tig) * LDP + rb + 8];                       \
                af[i][2] = Ab[(k + tig + 4) * LDP + rb];                       \
                af[i][3] = Ab[(k + tig + 4) * LDP + rb + 8];                   \
            }                                                                  \
            _Pragma("unroll")                                                  \
            for (int j = 0; j < 8; j++) {                                      \
                int nb = wn + j * 8 + g;                                       \
                bf_[j][0] = Wb[(k + tig) * LDP + nb];                          \
                bf_[j][1] = Wb[(k + tig + 4) * LDP + nb];                      \
            }                                                                  \
            _Pragma("unroll")                                                  \
            for (int i = 0; i < 2; i++)                                        \
                _Pragma("unroll")                                              \
                for (int j = 0; j < 8; j++)                                    \
                    mma_tf32(acc[i][j], af[i], bf_[j]);                        \
        }                                                                      \
    } while (0)

    GLOAD(0);
    SSTORE(0);
    __syncthreads();

    for (int s = 0; s < S; s++) {
        int bf = s & 1;
        if (s + 1 < S) GLOAD((s + 1) * 16);
        COMPUTE(bf);
        if (s + 1 < S) {
            SSTORE(bf ^ 1);
            __syncthreads();
        }
    }

#undef GLOAD
#undef SSTORE
#undef COMPUTE

    // epilogue: bias (+ReLU), float2 stores
    #pragma unroll
    for (int j = 0; j < 8; j++) {
        int col = n0 + wn + j * 8 + 2 * tig;
        float2 bv = *(const float2*)(bias + col);
        #pragma unroll
        for (int i = 0; i < 2; i++) {
            int row0 = m0 + wm + i * 16 + g;
            float v0 = acc[i][j][0] + bv.x;
            float v1 = acc[i][j][1] + bv.y;
            float v2 = acc[i][j][2] + bv.x;
            float v3 = acc[i][j][3] + bv.y;
            if (act) {
                v0 = fmaxf(v0, 0.f); v1 = fmaxf(v1, 0.f);
                v2 = fmaxf(v2, 0.f); v3 = fmaxf(v3, 0.f);
            }
            *(float2*)(C + (size_t)row0 * Nout + col)       = make_float2(v0, v1);
            *(float2*)(C + (size_t)(row0 + 8) * Nout + col) = make_float2(v2, v3);
        }
    }
}

// ---------------- fp32 SIMT GEMM (embedding only: K=92) ---------------------
__global__ __launch_bounds__(256) void gemm_f32(
    const float* __restrict__ Aext,
    const float* __restrict__ W, const float* __restrict__ bias,
    int cid, int M, int K, int Nout)
{
    __shared__ __align__(16) float As[2][16][132];
    __shared__ __align__(16) float Ws[2][16][132];

    const float* A = Aext;
    float*       C = buf_ptr(cid);

    const int tid = threadIdx.x;
    const int tx = tid & 15;
    const int ty = tid >> 4;
    const int m0 = blockIdx.y * 128;
    const int n0 = blockIdx.x * 128;

    const int lr = tid >> 2;
    const int lc = (tid & 3) * 4;

    const float* Ap0 = A + (size_t)(m0 + lr) * K;
    const float* Ap1 = A + (size_t)(m0 + lr + 64) * K;
    const float* Wp0 = W + (size_t)(n0 + lr) * K;
    const float* Wp1 = W + (size_t)(n0 + lr + 64) * K;

    float acc[8][8];
    #pragma unroll
    for (int i = 0; i < 8; i++)
        #pragma unroll
        for (int j = 0; j < 8; j++) acc[i][j] = 0.f;

    float4 ra0, ra1, rw0, rw1;
    const int ktiles = (K + 15) >> 4;

#define GLOAD(k0)                                                            \
    do {                                                                     \
        float* p0 = (float*)&ra0; float* p1 = (float*)&ra1;                  \
        float* q0 = (float*)&rw0; float* q1 = (float*)&rw1;                  \
        _Pragma("unroll")                                                    \
        for (int i = 0; i < 4; i++) {                                        \
            int kg = (k0) + lc + i;                                          \
            bool ok = (kg < K);                                              \
            p0[i] = ok ? Ap0[kg] : 0.f;                                      \
            p1[i] = ok ? Ap1[kg] : 0.f;                                      \
            q0[i] = ok ? Wp0[kg] : 0.f;                                      \
            q1[i] = ok ? Wp1[kg] : 0.f;                                      \
        }                                                                    \
    } while (0)

#define SSTORE(bf)                                                           \
    do {                                                                     \
        As[bf][lc + 0][lr]      = ra0.x; As[bf][lc + 1][lr]      = ra0.y;    \
        As[bf][lc + 2][lr]      = ra0.z; As[bf][lc + 3][lr]      = ra0.w;    \
        As[bf][lc + 0][lr + 64] = ra1.x; As[bf][lc + 1][lr + 64] = ra1.y;    \
        As[bf][lc + 2][lr + 64] = ra1.z; As[bf][lc + 3][lr + 64] = ra1.w;    \
        Ws[bf][lc + 0][lr]      = rw0.x; Ws[bf][lc + 1][lr]      = rw0.y;    \
        Ws[bf][lc + 2][lr]      = rw0.z; Ws[bf][lc + 3][lr]      = rw0.w;    \
        Ws[bf][lc + 0][lr + 64] = rw1.x; Ws[bf][lc + 1][lr + 64] = rw1.y;    \
        Ws[bf][lc + 2][lr + 64] = rw1.z; Ws[bf][lc + 3][lr + 64] = rw1.w;    \
    } while (0)

#define COMPUTE(bf)                                                          \
    do {                                                                     \
        _Pragma("unroll")                                                    \
        for (int k = 0; k < 16; k++) {                                       \
            float4 a0 = *(const float4*)(&As[bf][k][ty * 8]);                \
            float4 a1 = *(const float4*)(&As[bf][k][ty * 8 + 4]);            \
            float4 b0 = *(const float4*)(&Ws[bf][k][tx * 8]);                \
            float4 b1 = *(const float4*)(&Ws[bf][k][tx * 8 + 4]);            \
            float ar[8] = {a0.x, a0.y, a0.z, a0.w, a1.x, a1.y, a1.z, a1.w};  \
            float br[8] = {b0.x, b0.y, b0.z, b0.w, b1.x, b1.y, b1.z, b1.w};  \
            _Pragma("unroll")                                                \
            for (int i = 0; i < 8; i++)                                      \
                _Pragma("unroll")                                            \
                for (int j = 0; j < 8; j++)                                  \
                    acc[i][j] = fmaf(ar[i], br[j], acc[i][j]);               \
        }                                                                    \
    } while (0)

    GLOAD(0);
    SSTORE(0);
    __syncthreads();

    for (int kt = 0; kt < ktiles; kt++) {
        int bf = kt & 1;
        if (kt + 1 < ktiles) GLOAD((kt + 1) * 16);
        COMPUTE(bf);
        if (kt + 1 < ktiles) {
            SSTORE(bf ^ 1);
            __syncthreads();
        }
    }
#undef GLOAD
#undef SSTORE
#undef COMPUTE

    float4 bia0 = *(const float4*)(bias + n0 + tx * 8);
    float4 bia1 = *(const float4*)(bias + n0 + tx * 8 + 4);
    float bb[8] = {bia0.x, bia0.y, bia0.z, bia0.w, bia1.x, bia1.y, bia1.z, bia1.w};

    #pragma unroll
    for (int i = 0; i < 8; i++) {
        int m = m0 + ty * 8 + i;
        float* Crow = C + (size_t)m * Nout + n0 + tx * 8;
        float r[8];
        #pragma unroll
        for (int j = 0; j < 8; j++) r[j] = acc[i][j] + bb[j];
        *(float4*)(Crow)     = make_float4(r[0], r[1], r[2], r[3]);
        *(float4*)(Crow + 4) = make_float4(r[4], r[5], r[6], r[7]);
    }
}

// ---------------- ragged per-graph flash attention --------------------------
__global__ __launch_bounds__(256) void attn_kernel()
{
    int b  = blockIdx.x;
    int h  = blockIdx.y;
    int qt = blockIdx.z;
    int cnt = g_counts[b];
    int q0  = qt * 32;
    if (q0 >= cnt) return;
    int start = g_starts[b];
    int nq = min(32, cnt - q0);

    __shared__ float Qs[32][65];
    __shared__ float Ks[32][65];
    __shared__ float Vs[32][65];
    __shared__ float Sc[32][33];

    int tid = threadIdx.x;

    for (int idx = tid; idx < 32 * 64; idx += 256) {
        int r = idx >> 6, d = idx & 63;
        Qs[r][d] = (r < nq)
            ? g_qkv[(size_t)(start + q0 + r) * (3 * DM) + h * HD + d] : 0.f;
    }

    int q  = tid >> 3;
    int dg = tid & 7;
    int d0 = dg * 8;

    float acc[8];
    #pragma unroll
    for (int i = 0; i < 8; i++) acc[i] = 0.f;
    float mloc = -INFINITY, lloc = 0.f;
    const float scale = 0.125f;

    for (int k0 = 0; k0 < cnt; k0 += 32) {
        int nk = min(32, cnt - k0);
        __syncthreads();
        for (int idx = tid; idx < 32 * 64; idx += 256) {
            int r = idx >> 6, d = idx & 63;
            if (r < nk) {
                size_t base = (size_t)(start + k0 + r) * (3 * DM) + h * HD + d;
                Ks[r][d] = g_qkv[base + DM];
                Vs[r][d] = g_qkv[base + 2 * DM];
            }
        }
        __syncthreads();

        float s[4] = {0.f, 0.f, 0.f, 0.f};
        for (int d = 0; d < 64; d++) {
            float qv = Qs[q][d];
            #pragma unroll
            for (int kk = 0; kk < 4; kk++)
                s[kk] = fmaf(qv, Ks[dg * 4 + kk][d], s[kk]);
        }
        #pragma unroll
        for (int kk = 0; kk < 4; kk++) {
            int k = dg * 4 + kk;
            Sc[q][k] = (k < nk) ? s[kk] * scale : -INFINITY;
        }
        __syncthreads();

        float mc = -INFINITY;
        #pragma unroll
        for (int k = 0; k < 32; k++) mc = fmaxf(mc, Sc[q][k]);
        float mnew = fmaxf(mloc, mc);
        float corr = (mloc == -INFINITY) ? 0.f : __expf(mloc - mnew);
        lloc *= corr;
        #pragma unroll
        for (int i = 0; i < 8; i++) acc[i] *= corr;
        for (int k = 0; k < nk; k++) {
            float p = __expf(Sc[q][k] - mnew);
            lloc += p;
            #pragma unroll
            for (int i = 0; i < 8; i++)
                acc[i] = fmaf(p, Vs[k][d0 + i], acc[i]);
        }
        mloc = mnew;
        __syncthreads();
    }

    if (q < nq) {
        float inv = 1.f / lloc;
        size_t base = (size_t)(start + q0 + q) * DM + h * HD + d0;
        #pragma unroll
        for (int i = 0; i < 8; i++) g_tmp[base + i] = acc[i] * inv;
    }
}

// ---------------- residual + layernorm --------------------------------------
__global__ __launch_bounds__(128) void ln_kernel(
    int rid, int did, int oid,
    const float* __restrict__ gg, const float* __restrict__ bb)
{
    const float* resid = buf_ptr(rid);
    const float* delta = buf_ptr(did);
    float*       out   = buf_ptr(oid);

    int row = blockIdx.x;
    int tid = threadIdx.x;
    size_t base = (size_t)row * DM;

    float v[4];
    float s = 0.f, sq = 0.f;
    #pragma unroll
    for (int i = 0; i < 4; i++) {
        int c = tid + i * 128;
        float x = resid[base + c] + delta[base + c];
        v[i] = x;
        s += x; sq += x * x;
    }
    __shared__ float shs[4], shq[4];
    #pragma unroll
    for (int o = 16; o > 0; o >>= 1) {
        s  += __shfl_down_sync(0xffffffffu, s, o);
        sq += __shfl_down_sync(0xffffffffu, sq, o);
    }
    int w = tid >> 5;
    if ((tid & 31) == 0) { shs[w] = s; shq[w] = sq; }
    __syncthreads();
    float ts = shs[0] + shs[1] + shs[2] + shs[3];
    float tq = shq[0] + shq[1] + shq[2] + shq[3];
    float mean = ts * (1.f / DM);
    float var  = tq * (1.f / DM) - mean * mean;
    float inv  = rsqrtf(fmaxf(var, 0.f) + LN_EPS);
    #pragma unroll
    for (int i = 0; i < 4; i++) {
        int c = tid + i * 128;
        out[base + c] = (v[i] - mean) * inv * gg[c] + bb[c];
    }
}

// ---------------- segment mean pool -----------------------------------------
__global__ __launch_bounds__(256) void pool_kernel()
{
    int b = blockIdx.x;
    int tid = threadIdx.x;
    int cnt = g_counts[b], st = g_starts[b];
    float a0 = 0.f, a1 = 0.f;
    for (int r = 0; r < cnt; r++) {
        size_t base = (size_t)(st + r) * DM;
        a0 += g_h[base + tid];
        a1 += g_h[base + tid + 256];
    }
    float inv = (cnt > 0) ? 1.f / (float)cnt : 0.f;
    g_pooled[b * DM + tid]       = a0 * inv;
    g_pooled[b * DM + tid + 256] = a1 * inv;
}

// ---------------- head ------------------------------------------------------
__global__ __launch_bounds__(256) void head_kernel(
    const float* __restrict__ w1, const float* __restrict__ b1,
    const float* __restrict__ w2, const float* __restrict__ b2,
    float* __restrict__ out)
{
    int b = blockIdx.x;
    int tid = threadIdx.x;
    __shared__ float ps[DM];
    ps[tid]       = g_pooled[b * DM + tid];
    ps[tid + 256] = g_pooled[b * DM + tid + 256];
    __syncthreads();

    int warp = tid >> 5, lane = tid & 31;
    float partial = 0.f;
    for (int j = warp; j < DM; j += 8) {
        float a = 0.f;
        const float* wr = w1 + (size_t)j * DM;
        for (int k = lane; k < DM; k += 32) a = fmaf(ps[k], wr[k], a);
        #pragma unroll
        for (int o = 16; o > 0; o >>= 1) a += __shfl_down_sync(0xffffffffu, a, o);
        if (lane == 0) {
            a += b1[j];
            float sil = a / (1.f + __expf(-a));
            partial = fmaf(sil, w2[j], partial);
        }
    }
    __shared__ float red[8];
    if (lane == 0) red[warp] = partial;
    __syncthreads();
    if (tid == 0) {
        float t = 0.f;
        #pragma unroll
        for (int i = 0; i < 8; i++) t += red[i];
        out[b] = t + b2[0];
    }
}

// ---------------- launch -----------------------------------------------------
extern "C" void kernel_launch(void* const* d_in, const int* in_sizes, int n_in,
                              void* d_out, int out_size)
{
    const float* node_features = (const float*)d_in[0];
    const int*   batch32       = (const int*)d_in[3];
    const float* emb_w    = (const float*)d_in[4];
    const float* emb_b    = (const float*)d_in[5];
    const float* in_proj_w = (const float*)d_in[6];
    const float* in_proj_b = (const float*)d_in[7];
    const float* out_w    = (const float*)d_in[8];
    const float* out_b    = (const float*)d_in[9];
    const float* ln1_g    = (const float*)d_in[10];
    const float* ln1_b    = (const float*)d_in[11];
    const float* ffn_w1   = (const float*)d_in[12];
    const float* ffn_b1   = (const float*)d_in[13];
    const float* ffn_w2   = (const float*)d_in[14];
    const float* ffn_b2   = (const float*)d_in[15];
    const float* ln2_g    = (const float*)d_in[16];
    const float* ln2_b    = (const float*)d_in[17];
    const float* head_w1  = (const float*)d_in[18];
    const float* head_b1  = (const float*)d_in[19];
    const float* head_w2  = (const float*)d_in[20];
    const float* head_b2  = (const float*)d_in[21];
    float* out = (float*)d_out;

    cudaFuncSetAttribute(gemm_tc, cudaFuncAttributeMaxDynamicSharedMemorySize,
                         GEMM_SMEM);

    k_bookkeep<<<1, 256>>>(batch32);

    // embedding (fp32, K=92)
    gemm_f32<<<dim3(DM / 128, NN / 128), 256>>>(
        node_features, emb_w, emb_b, BUF_H, NN, DIN, DM);

    for (int l = 0; l < NL; l++) {
        const float* ipw = in_proj_w + (size_t)l * 3 * DM * DM;
        const float* ipb = in_proj_b + (size_t)l * 3 * DM;
        const float* ow  = out_w + (size_t)l * DM * DM;
        const float* ob  = out_b + (size_t)l * DM;
        const float* f1w = ffn_w1 + (size_t)l * DFF * DM;
        const float* f1b = ffn_b1 + (size_t)l * DFF;
        const float* f2w = ffn_w2 + (size_t)l * DM * DFF;
        const float* f2b = ffn_b2 + (size_t)l * DM;

        gemm_tc<<<dim3(3 * DM / 128, NN / 128), 256, GEMM_SMEM>>>(
            BUF_H, ipw, ipb, BUF_QKV, NN, DM, 3 * DM, 0);

        attn_kernel<<<dim3(BG, NH, 16), 256>>>();

        gemm_tc<<<dim3(DM / 128, NN / 128), 256, GEMM_SMEM>>>(
            BUF_TMP, ow, ob, BUF_X, NN, DM, DM, 0);

        ln_kernel<<<NN, 128>>>(BUF_H, BUF_X, BUF_X,
                               ln1_g + (size_t)l * DM, ln1_b + (size_t)l * DM);

        gemm_tc<<<dim3(DFF / 128, NN / 128), 256, GEMM_SMEM>>>(
            BUF_X, f1w, f1b, BUF_FFN, NN, DM, DFF, 1);

        gemm_tc<<<dim3(DM / 128, NN / 128), 256, GEMM_SMEM>>>(
            BUF_FFN, f2w, f2b, BUF_TMP, NN, DFF, DM, 0);

        ln_kernel<<<NN, 128>>>(BUF_X, BUF_TMP, BUF_H,
                               ln2_g + (size_t)l * DM, ln2_b + (size_t)l * DM);
    }

    pool_kernel<<<BG, 256>>>();
    head_kernel<<<BG, 256>>>(head_w1, head_b1, head_w2, head_b2, out);
}

// round 11
// speedup vs baseline: 4.7756x; 1.8528x over previous
#include <cuda_runtime.h>
#include <math.h>
#include <stdint.h>

#define NN   24576
#define DIN  92
#define DM   512
#define NH   8
#define HD   64
#define NL   3
#define DFF  2048
#define BG   128
#define LN_EPS 1e-5f

// ---------------- scratch (static device globals; no allocs allowed) --------
__device__ float g_h[(size_t)NN * DM];
__device__ float g_qkv[(size_t)NN * 3 * DM];
__device__ float g_tmp[(size_t)NN * DM];
__device__ float g_x[(size_t)NN * DM];
__device__ float g_ffn[(size_t)NN * DFF];
__device__ float g_pooled[BG * DM];
__device__ int   g_counts[BG];
__device__ int   g_starts[BG];

#define BUF_H    0
#define BUF_QKV  1
#define BUF_TMP  2
#define BUF_X    3
#define BUF_FFN  4

__device__ __forceinline__ float* buf_ptr(int id) {
    switch (id) {
        case BUF_H:   return g_h;
        case BUF_QKV: return g_qkv;
        case BUF_TMP: return g_tmp;
        case BUF_X:   return g_x;
        default:      return g_ffn;
    }
}

// ---------------- graph bookkeeping -----------------------------------------
__global__ __launch_bounds__(256) void k_bookkeep(const int* __restrict__ b32)
{
    __shared__ int s_cnt[BG];
    __shared__ int s_any;
    int tid = threadIdx.x;

    if (tid == 0) s_any = 0;
    for (int i = tid; i < BG; i += 256) s_cnt[i] = 0;
    __syncthreads();

    int any = 0;
    for (int i = (NN / 2) + 1 + 2 * tid; i < NN; i += 2 * 256)
        if (b32[i] != 0) any = 1;
    if (any) atomicOr(&s_any, 1);
    __syncthreads();
    int is64 = (s_any == 0);

    for (int i = tid; i < NN; i += 256) {
        int v = is64 ? b32[2 * i] : b32[i];
        v = min(max(v, 0), BG - 1);
        atomicAdd(&s_cnt[v], 1);
    }
    __syncthreads();

    if (tid == 0) {
        int s = 0;
        for (int i = 0; i < BG; i++) {
            g_counts[i] = s_cnt[i];
            g_starts[i] = s;
            s += s_cnt[i];
        }
    }
}

// ---------------- fp16 warp-MMA helpers --------------------------------------
// pack two floats -> f16x2 (lo = even k, hi = odd k)
__device__ __forceinline__ uint32_t pack_f16x2(float even, float odd) {
    uint32_t r;
    asm("cvt.rn.f16x2.f32 %0, %1, %2;" : "=r"(r) : "f"(odd), "f"(even));
    return r;
}

__device__ __forceinline__ void mma_f16(float* c, const uint32_t* a, const uint32_t* b) {
    asm volatile(
        "mma.sync.aligned.m16n8k16.row.col.f32.f16.f16.f32 "
        "{%0,%1,%2,%3}, {%4,%5,%6,%7}, {%8,%9}, {%0,%1,%2,%3};"
        : "+f"(c[0]), "+f"(c[1]), "+f"(c[2]), "+f"(c[3])
        : "r"(a[0]), "r"(a[1]), "r"(a[2]), "r"(a[3]), "r"(b[0]), "r"(b[1]));
}

// ---------------- fp16 tensor GEMM: C[M,Nout] = A[M,K] @ W[Nout,K]^T + bias -
// 128x128 tile, BK=32 (f16), double-buffered, 256 threads (8 warps, 4x2),
// warp tile 32x64 via m16n8k16. K must be a multiple of 32.
// smem row stride: 40 halves = 20 words (conflict-free fragment LDS).
#define LDW 20                                  // words per smem row
#define TILE_W (128 * LDW)                      // words per 128x32 tile
#define GEMM_SMEM (4 * TILE_W * 4)              // A0,A1,W0,W1 = 40960 bytes

__global__ void __launch_bounds__(256, 2) gemm_tc(
    int aid, const float* __restrict__ W, const float* __restrict__ bias,
    int cid, int M, int K, int Nout, int act)
{
    extern __shared__ uint32_t dsm[];
    uint32_t* Abuf[2] = {dsm, dsm + TILE_W};
    uint32_t* Wbuf[2] = {dsm + 2 * TILE_W, dsm + 3 * TILE_W};

    const float* A = buf_ptr(aid);
    float*       C = buf_ptr(cid);

    const int tid  = threadIdx.x;
    const int warp = tid >> 5;
    const int lane = tid & 31;
    const int g    = lane >> 2;          // 0..7
    const int tig  = lane & 3;           // 0..3
    const int wm   = (warp >> 1) * 32;   // warp row offset
    const int wn   = (warp & 1) * 64;    // warp col offset

    const int m0 = blockIdx.y * 128;
    const int n0 = blockIdx.x * 128;

    // loader: thread t -> row t>>1 (0..127), k-half (t&1)*16
    const int lrow  = tid >> 1;
    const int lhalf = tid & 1;

    const float* Apt = A + (size_t)(m0 + lrow) * K + lhalf * 16;
    const float* Wpt = W + (size_t)(n0 + lrow) * K + lhalf * 16;
    const int swbase = lrow * LDW + lhalf * 8;   // word offset in tile

    float acc[2][8][4];
    #pragma unroll
    for (int i = 0; i < 2; i++)
        #pragma unroll
        for (int j = 0; j < 8; j++)
            #pragma unroll
            for (int r = 0; r < 4; r++) acc[i][j][r] = 0.f;

    float4 ra[4], rw[4];
    const int S = K >> 5;

#define GLOAD(k0)                                              \
    do {                                                       \
        _Pragma("unroll")                                      \
        for (int i = 0; i < 4; i++) {                          \
            ra[i] = *(const float4*)(Apt + (k0) + i * 4);      \
            rw[i] = *(const float4*)(Wpt + (k0) + i * 4);      \
        }                                                      \
    } while (0)

#define SSTORE(bf)                                                              \
    do {                                                                        \
        uint32_t* Ab = Abuf[bf];                                                \
        uint32_t* Wb = Wbuf[bf];                                                \
        _Pragma("unroll")                                                       \
        for (int i = 0; i < 4; i++) {                                           \
            uint32_t pa0 = pack_f16x2(ra[i].x, ra[i].y);                        \
            uint32_t pa1 = pack_f16x2(ra[i].z, ra[i].w);                        \
            uint32_t pw0 = pack_f16x2(rw[i].x, rw[i].y);                        \
            uint32_t pw1 = pack_f16x2(rw[i].z, rw[i].w);                        \
            *(uint2*)(Ab + swbase + 2 * i) = make_uint2(pa0, pa1);              \
            *(uint2*)(Wb + swbase + 2 * i) = make_uint2(pw0, pw1);              \
        }                                                                       \
    } while (0)

#define COMPUTE(bf)                                                             \
    do {                                                                        \
        const uint32_t* Ab = Abuf[bf];                                          \
        const uint32_t* Wb = Wbuf[bf];                                          \
        _Pragma("unroll")                                                       \
        for (int ks = 0; ks < 2; ks++) {                                        \
            const int kw = ks * 8;                                              \
            uint32_t af[2][4], bfr[8][2];                                       \
            _Pragma("unroll")                                                   \
            for (int i = 0; i < 2; i++) {                                       \
                int rb = wm + i * 16 + g;                                       \
                af[i][0] = Ab[rb * LDW + kw + tig];                             \
                af[i][1] = Ab[(rb + 8) * LDW + kw + tig];                       \
                af[i][2] = Ab[rb * LDW + kw + tig + 4];                         \
                af[i][3] = Ab[(rb + 8) * LDW + kw + tig + 4];                   \
            }                                                                   \
            _Pragma("unroll")                                                   \
            for (int j = 0; j < 8; j++) {                                       \
                int nb = wn + j * 8 + g;                                        \
                bfr[j][0] = Wb[nb * LDW + kw + tig];                            \
                bfr[j][1] = Wb[nb * LDW + kw + tig + 4];                        \
            }                                                                   \
            _Pragma("unroll")                                                   \
            for (int i = 0; i < 2; i++)                                         \
                _Pragma("unroll")                                               \
                for (int j = 0; j < 8; j++)                                     \
                    mma_f16(acc[i][j], af[i], bfr[j]);                          \
        }                                                                       \
    } while (0)

    GLOAD(0);
    SSTORE(0);
    __syncthreads();

    for (int s = 0; s < S; s++) {
        int bf = s & 1;
        if (s + 1 < S) GLOAD((s + 1) * 32);
        COMPUTE(bf);
        if (s + 1 < S) {
            SSTORE(bf ^ 1);
            __syncthreads();
        }
    }

#undef GLOAD
#undef SSTORE
#undef COMPUTE

    // epilogue: bias (+ReLU), float2 stores
    #pragma unroll
    for (int j = 0; j < 8; j++) {
        int col = n0 + wn + j * 8 + 2 * tig;
        float2 bv = *(const float2*)(bias + col);
        #pragma unroll
        for (int i = 0; i < 2; i++) {
            int row0 = m0 + wm + i * 16 + g;
            float v0 = acc[i][j][0] + bv.x;
            float v1 = acc[i][j][1] + bv.y;
            float v2 = acc[i][j][2] + bv.x;
            float v3 = acc[i][j][3] + bv.y;
            if (act) {
                v0 = fmaxf(v0, 0.f); v1 = fmaxf(v1, 0.f);
                v2 = fmaxf(v2, 0.f); v3 = fmaxf(v3, 0.f);
            }
            *(float2*)(C + (size_t)row0 * Nout + col)       = make_float2(v0, v1);
            *(float2*)(C + (size_t)(row0 + 8) * Nout + col) = make_float2(v2, v3);
        }
    }
}

// ---------------- fp32 SIMT GEMM (embedding only: K=92) ---------------------
__global__ __launch_bounds__(256) void gemm_f32(
    const float* __restrict__ Aext,
    const float* __restrict__ W, const float* __restrict__ bias,
    int cid, int M, int K, int Nout)
{
    __shared__ __align__(16) float As[2][16][132];
    __shared__ __align__(16) float Ws[2][16][132];

    const float* A = Aext;
    float*       C = buf_ptr(cid);

    const int tid = threadIdx.x;
    const int tx = tid & 15;
    const int ty = tid >> 4;
    const int m0 = blockIdx.y * 128;
    const int n0 = blockIdx.x * 128;

    const int lr = tid >> 2;
    const int lc = (tid & 3) * 4;

    const float* Ap0 = A + (size_t)(m0 + lr) * K;
    const float* Ap1 = A + (size_t)(m0 + lr + 64) * K;
    const float* Wp0 = W + (size_t)(n0 + lr) * K;
    const float* Wp1 = W + (size_t)(n0 + lr + 64) * K;

    float acc[8][8];
    #pragma unroll
    for (int i = 0; i < 8; i++)
        #pragma unroll
        for (int j = 0; j < 8; j++) acc[i][j] = 0.f;

    float4 ra0, ra1, rw0, rw1;
    const int ktiles = (K + 15) >> 4;

#define GLOAD(k0)                                                            \
    do {                                                                     \
        float* p0 = (float*)&ra0; float* p1 = (float*)&ra1;                  \
        float* q0 = (float*)&rw0; float* q1 = (float*)&rw1;                  \
        _Pragma("unroll")                                                    \
        for (int i = 0; i < 4; i++) {                                        \
            int kg = (k0) + lc + i;                                          \
            bool ok = (kg < K);                                              \
            p0[i] = ok ? Ap0[kg] : 0.f;                                      \
            p1[i] = ok ? Ap1[kg] : 0.f;                                      \
            q0[i] = ok ? Wp0[kg] : 0.f;                                      \
            q1[i] = ok ? Wp1[kg] : 0.f;                                      \
        }                                                                    \
    } while (0)

#define SSTORE(bf)                                                           \
    do {                                                                     \
        As[bf][lc + 0][lr]      = ra0.x; As[bf][lc + 1][lr]      = ra0.y;    \
        As[bf][lc + 2][lr]      = ra0.z; As[bf][lc + 3][lr]      = ra0.w;    \
        As[bf][lc + 0][lr + 64] = ra1.x; As[bf][lc + 1][lr + 64] = ra1.y;    \
        As[bf][lc + 2][lr + 64] = ra1.z; As[bf][lc + 3][lr + 64] = ra1.w;    \
        Ws[bf][lc + 0][lr]      = rw0.x; Ws[bf][lc + 1][lr]      = rw0.y;    \
        Ws[bf][lc + 2][lr]      = rw0.z; Ws[bf][lc + 3][lr]      = rw0.w;    \
        Ws[bf][lc + 0][lr + 64] = rw1.x; Ws[bf][lc + 1][lr + 64] = rw1.y;    \
        Ws[bf][lc + 2][lr + 64] = rw1.z; Ws[bf][lc + 3][lr + 64] = rw1.w;    \
    } while (0)

#define COMPUTE(bf)                                                          \
    do {                                                                     \
        _Pragma("unroll")                                                    \
        for (int k = 0; k < 16; k++) {                                       \
            float4 a0 = *(const float4*)(&As[bf][k][ty * 8]);                \
            float4 a1 = *(const float4*)(&As[bf][k][ty * 8 + 4]);            \
            float4 b0 = *(const float4*)(&Ws[bf][k][tx * 8]);                \
            float4 b1 = *(const float4*)(&Ws[bf][k][tx * 8 + 4]);            \
            float ar[8] = {a0.x, a0.y, a0.z, a0.w, a1.x, a1.y, a1.z, a1.w};  \
            float br[8] = {b0.x, b0.y, b0.z, b0.w, b1.x, b1.y, b1.z, b1.w};  \
            _Pragma("unroll")                                                \
            for (int i = 0; i < 8; i++)                                      \
                _Pragma("unroll")                                            \
                for (int j = 0; j < 8; j++)                                  \
                    acc[i][j] = fmaf(ar[i], br[j], acc[i][j]);               \
        }                                                                    \
    } while (0)

    GLOAD(0);
    SSTORE(0);
    __syncthreads();

    for (int kt = 0; kt < ktiles; kt++) {
        int bf = kt & 1;
        if (kt + 1 < ktiles) GLOAD((kt + 1) * 16);
        COMPUTE(bf);
        if (kt + 1 < ktiles) {
            SSTORE(bf ^ 1);
            __syncthreads();
        }
    }
#undef GLOAD
#undef SSTORE
#undef COMPUTE

    float4 bia0 = *(const float4*)(bias + n0 + tx * 8);
    float4 bia1 = *(const float4*)(bias + n0 + tx * 8 + 4);
    float bb[8] = {bia0.x, bia0.y, bia0.z, bia0.w, bia1.x, bia1.y, bia1.z, bia1.w};

    #pragma unroll
    for (int i = 0; i < 8; i++) {
        int m = m0 + ty * 8 + i;
        float* Crow = C + (size_t)m * Nout + n0 + tx * 8;
        float r[8];
        #pragma unroll
        for (int j = 0; j < 8; j++) r[j] = acc[i][j] + bb[j];
        *(float4*)(Crow)     = make_float4(r[0], r[1], r[2], r[3]);
        *(float4*)(Crow + 4) = make_float4(r[4], r[5], r[6], r[7]);
    }
}

// ---------------- ragged per-graph flash attention --------------------------
__global__ __launch_bounds__(256) void attn_kernel()
{
    int b  = blockIdx.x;
    int h  = blockIdx.y;
    int qt = blockIdx.z;
    int cnt = g_counts[b];
    int q0  = qt * 32;
    if (q0 >= cnt) return;
    int start = g_starts[b];
    int nq = min(32, cnt - q0);

    __shared__ float Qs[32][65];
    __shared__ float Ks[32][65];
    __shared__ float Vs[32][65];
    __shared__ float Sc[32][33];

    int tid = threadIdx.x;

    for (int idx = tid; idx < 32 * 64; idx += 256) {
        int r = idx >> 6, d = idx & 63;
        Qs[r][d] = (r < nq)
            ? g_qkv[(size_t)(start + q0 + r) * (3 * DM) + h * HD + d] : 0.f;
    }

    int q  = tid >> 3;
    int dg = tid & 7;
    int d0 = dg * 8;

    float acc[8];
    #pragma unroll
    for (int i = 0; i < 8; i++) acc[i] = 0.f;
    float mloc = -INFINITY, lloc = 0.f;
    const float scale = 0.125f;

    for (int k0 = 0; k0 < cnt; k0 += 32) {
        int nk = min(32, cnt - k0);
        __syncthreads();
        for (int idx = tid; idx < 32 * 64; idx += 256) {
            int r = idx >> 6, d = idx & 63;
            if (r < nk) {
                size_t base = (size_t)(start + k0 + r) * (3 * DM) + h * HD + d;
                Ks[r][d] = g_qkv[base + DM];
                Vs[r][d] = g_qkv[base + 2 * DM];
            }
        }
        __syncthreads();

        float s[4] = {0.f, 0.f, 0.f, 0.f};
        for (int d = 0; d < 64; d++) {
            float qv = Qs[q][d];
            #pragma unroll
            for (int kk = 0; kk < 4; kk++)
                s[kk] = fmaf(qv, Ks[dg * 4 + kk][d], s[kk]);
        }
        #pragma unroll
        for (int kk = 0; kk < 4; kk++) {
            int k = dg * 4 + kk;
            Sc[q][k] = (k < nk) ? s[kk] * scale : -INFINITY;
        }
        __syncthreads();

        float mc = -INFINITY;
        #pragma unroll
        for (int k = 0; k < 32; k++) mc = fmaxf(mc, Sc[q][k]);
        float mnew = fmaxf(mloc, mc);
        float corr = (mloc == -INFINITY) ? 0.f : __expf(mloc - mnew);
        lloc *= corr;
        #pragma unroll
        for (int i = 0; i < 8; i++) acc[i] *= corr;
        for (int k = 0; k < nk; k++) {
            float p = __expf(Sc[q][k] - mnew);
            lloc += p;
            #pragma unroll
            for (int i = 0; i < 8; i++)
                acc[i] = fmaf(p, Vs[k][d0 + i], acc[i]);
        }
        mloc = mnew;
        __syncthreads();
    }

    if (q < nq) {
        float inv = 1.f / lloc;
        size_t base = (size_t)(start + q0 + q) * DM + h * HD + d0;
        #pragma unroll
        for (int i = 0; i < 8; i++) g_tmp[base + i] = acc[i] * inv;
    }
}

// ---------------- residual + layernorm --------------------------------------
__global__ __launch_bounds__(128) void ln_kernel(
    int rid, int did, int oid,
    const float* __restrict__ gg, const float* __restrict__ bb)
{
    const float* resid = buf_ptr(rid);
    const float* delta = buf_ptr(did);
    float*       out   = buf_ptr(oid);

    int row = blockIdx.x;
    int tid = threadIdx.x;
    size_t base = (size_t)row * DM;

    float v[4];
    float s = 0.f, sq = 0.f;
    #pragma unroll
    for (int i = 0; i < 4; i++) {
        int c = tid + i * 128;
        float x = resid[base + c] + delta[base + c];
        v[i] = x;
        s += x; sq += x * x;
    }
    __shared__ float shs[4], shq[4];
    #pragma unroll
    for (int o = 16; o > 0; o >>= 1) {
        s  += __shfl_down_sync(0xffffffffu, s, o);
        sq += __shfl_down_sync(0xffffffffu, sq, o);
    }
    int w = tid >> 5;
    if ((tid & 31) == 0) { shs[w] = s; shq[w] = sq; }
    __syncthreads();
    float ts = shs[0] + shs[1] + shs[2] + shs[3];
    float tq = shq[0] + shq[1] + shq[2] + shq[3];
    float mean = ts * (1.f / DM);
    float var  = tq * (1.f / DM) - mean * mean;
    float inv  = rsqrtf(fmaxf(var, 0.f) + LN_EPS);
    #pragma unroll
    for (int i = 0; i < 4; i++) {
        int c = tid + i * 128;
        out[base + c] = (v[i] - mean) * inv * gg[c] + bb[c];
    }
}

// ---------------- segment mean pool -----------------------------------------
__global__ __launch_bounds__(256) void pool_kernel()
{
    int b = blockIdx.x;
    int tid = threadIdx.x;
    int cnt = g_counts[b], st = g_starts[b];
    float a0 = 0.f, a1 = 0.f;
    for (int r = 0; r < cnt; r++) {
        size_t base = (size_t)(st + r) * DM;
        a0 += g_h[base + tid];
        a1 += g_h[base + tid + 256];
    }
    float inv = (cnt > 0) ? 1.f / (float)cnt : 0.f;
    g_pooled[b * DM + tid]       = a0 * inv;
    g_pooled[b * DM + tid + 256] = a1 * inv;
}

// ---------------- head ------------------------------------------------------
__global__ __launch_bounds__(256) void head_kernel(
    const float* __restrict__ w1, const float* __restrict__ b1,
    const float* __restrict__ w2, const float* __restrict__ b2,
    float* __restrict__ out)
{
    int b = blockIdx.x;
    int tid = threadIdx.x;
    __shared__ float ps[DM];
    ps[tid]       = g_pooled[b * DM + tid];
    ps[tid + 256] = g_pooled[b * DM + tid + 256];
    __syncthreads();

    int warp = tid >> 5, lane = tid & 31;
    float partial = 0.f;
    for (int j = warp; j < DM; j += 8) {
        float a = 0.f;
        const float* wr = w1 + (size_t)j * DM;
        for (int k = lane; k < DM; k += 32) a = fmaf(ps[k], wr[k], a);
        #pragma unroll
        for (int o = 16; o > 0; o >>= 1) a += __shfl_down_sync(0xffffffffu, a, o);
        if (lane == 0) {
            a += b1[j];
            float sil = a / (1.f + __expf(-a));
            partial = fmaf(sil, w2[j], partial);
        }
    }
    __shared__ float red[8];
    if (lane == 0) red[warp] = partial;
    __syncthreads();
    if (tid == 0) {
        float t = 0.f;
        #pragma unroll
        for (int i = 0; i < 8; i++) t += red[i];
        out[b] = t + b2[0];
    }
}

// ---------------- launch -----------------------------------------------------
extern "C" void kernel_launch(void* const* d_in, const int* in_sizes, int n_in,
                              void* d_out, int out_size)
{
    const float* node_features = (const float*)d_in[0];
    const int*   batch32       = (const int*)d_in[3];
    const float* emb_w    = (const float*)d_in[4];
    const float* emb_b    = (const float*)d_in[5];
    const float* in_proj_w = (const float*)d_in[6];
    const float* in_proj_b = (const float*)d_in[7];
    const float* out_w    = (const float*)d_in[8];
    const float* out_b    = (const float*)d_in[9];
    const float* ln1_g    = (const float*)d_in[10];
    const float* ln1_b    = (const float*)d_in[11];
    const float* ffn_w1   = (const float*)d_in[12];
    const float* ffn_b1   = (const float*)d_in[13];
    const float* ffn_w2   = (const float*)d_in[14];
    const float* ffn_b2   = (const float*)d_in[15];
    const float* ln2_g    = (const float*)d_in[16];
    const float* ln2_b    = (const float*)d_in[17];
    const float* head_w1  = (const float*)d_in[18];
    const float* head_b1  = (const float*)d_in[19];
    const float* head_w2  = (const float*)d_in[20];
    const float* head_b2  = (const float*)d_in[21];
    float* out = (float*)d_out;

    cudaFuncSetAttribute(gemm_tc, cudaFuncAttributeMaxDynamicSharedMemorySize,
                         GEMM_SMEM);

    k_bookkeep<<<1, 256>>>(batch32);

    // embedding (fp32, K=92)
    gemm_f32<<<dim3(DM / 128, NN / 128), 256>>>(
        node_features, emb_w, emb_b, BUF_H, NN, DIN, DM);

    for (int l = 0; l < NL; l++) {
        const float* ipw = in_proj_w + (size_t)l * 3 * DM * DM;
        const float* ipb = in_proj_b + (size_t)l * 3 * DM;
        const float* ow  = out_w + (size_t)l * DM * DM;
        const float* ob  = out_b + (size_t)l * DM;
        const float* f1w = ffn_w1 + (size_t)l * DFF * DM;
        const float* f1b = ffn_b1 + (size_t)l * DFF;
        const float* f2w = ffn_w2 + (size_t)l * DM * DFF;
        const float* f2b = ffn_b2 + (size_t)l * DM;

        gemm_tc<<<dim3(3 * DM / 128, NN / 128), 256, GEMM_SMEM>>>(
            BUF_H, ipw, ipb, BUF_QKV, NN, DM, 3 * DM, 0);

        attn_kernel<<<dim3(BG, NH, 16), 256>>>();

        gemm_tc<<<dim3(DM / 128, NN / 128), 256, GEMM_SMEM>>>(
            BUF_TMP, ow, ob, BUF_X, NN, DM, DM, 0);

        ln_kernel<<<NN, 128>>>(BUF_H, BUF_X, BUF_X,
                               ln1_g + (size_t)l * DM, ln1_b + (size_t)l * DM);

        gemm_tc<<<dim3(DFF / 128, NN / 128), 256, GEMM_SMEM>>>(
            BUF_X, f1w, f1b, BUF_FFN, NN, DM, DFF, 1);

        gemm_tc<<<dim3(DM / 128, NN / 128), 256, GEMM_SMEM>>>(
            BUF_FFN, f2w, f2b, BUF_TMP, NN, DFF, DM, 0);

        ln_kernel<<<NN, 128>>>(BUF_X, BUF_TMP, BUF_H,
                               ln2_g + (size_t)l * DM, ln2_b + (size_t)l * DM);
    }

    pool_kernel<<<BG, 256>>>();
    head_kernel<<<BG, 256>>>(head_w1, head_b1, head_w2, head_b2, out);
}

// round 12
// speedup vs baseline: 6.3275x; 1.3250x over previous
#include <cuda_runtime.h>
#include <cuda_fp16.h>
#include <math.h>
#include <stdint.h>

#define NN   24576
#define DIN  92
#define DM   512
#define NH   8
#define HD   64
#define NL   3
#define DFF  2048
#define BG   128
#define LN_EPS 1e-5f

// ---------------- scratch (static device globals; no allocs allowed) --------
__device__ float g_h[(size_t)NN * DM];          // f32 hidden (residual/pool)
__device__ float g_qkv[(size_t)NN * 3 * DM];    // f32 qkv / ffn2-out scratch
__device__ float g_x[(size_t)NN * DM];          // f32 post-LN1
__device__ float g_pooled[BG * DM];
__device__ int   g_counts[BG];
__device__ int   g_starts[BG];

__device__ __half g_h16[(size_t)NN * DM];       // f16 of hidden
__device__ __half g_x16[(size_t)NN * DM];       // f16 of post-LN1
__device__ __half g_t16[(size_t)NN * DM];       // f16 attn out
__device__ __half g_f16[(size_t)NN * DFF];      // f16 ffn hidden
__device__ __half g_w16[9437184];               // f16 weights (all layers)

// f32 buffer ids
#define BUF_H    0
#define BUF_QKV  1
#define BUF_X    2
__device__ __forceinline__ float* buf_ptr(int id) {
    switch (id) {
        case BUF_H:   return g_h;
        case BUF_QKV: return g_qkv;
        default:      return g_x;
    }
}
// f16 buffer ids
#define F16_H    0
#define F16_X    1
#define F16_T    2
#define F16_F    3
__device__ __forceinline__ __half* f16_ptr(int id) {
    switch (id) {
        case F16_H: return g_h16;
        case F16_X: return g_x16;
        case F16_T: return g_t16;
        default:    return g_f16;
    }
}

// weight offsets in g_w16 (halves)
#define IPW_OFF 0
#define IPW_PER (3 * DM * DM)          // 786432
#define OW_OFF  (3 * IPW_PER)          // 2359296
#define OW_PER  (DM * DM)              // 262144
#define F1W_OFF (OW_OFF + 3 * OW_PER)  // 3145728
#define F1W_PER (DFF * DM)             // 1048576
#define F2W_OFF (F1W_OFF + 3 * F1W_PER)// 6291456
#define F2W_PER (DM * DFF)             // 1048576

// ---------------- PTX helpers ------------------------------------------------
__device__ __forceinline__ uint32_t smem_u32(const void* p) {
    uint32_t a;
    asm("{ .reg .u64 t; cvta.to.shared.u64 t, %1; cvt.u32.u64 %0, t; }"
        : "=r"(a) : "l"(p));
    return a;
}
#define CPA16(dst, src) \
    asm volatile("cp.async.ca.shared.global [%0], [%1], 16;" :: "r"(dst), "l"(src))
#define CPCOMMIT() asm volatile("cp.async.commit_group;" ::: "memory")
#define CPWAIT1()  asm volatile("cp.async.wait_group 1;" ::: "memory")
#define CPWAIT0()  asm volatile("cp.async.wait_group 0;" ::: "memory")
#define LDMX4(r0, r1, r2, r3, a) \
    asm volatile("ldmatrix.sync.aligned.m8n8.x4.shared.b16 {%0,%1,%2,%3}, [%4];" \
                 : "=r"(r0), "=r"(r1), "=r"(r2), "=r"(r3) : "r"(a))

__device__ __forceinline__ void mma_f16(float* c, const uint32_t* a,
                                        uint32_t b0, uint32_t b1) {
    asm volatile(
        "mma.sync.aligned.m16n8k16.row.col.f32.f16.f16.f32 "
        "{%0,%1,%2,%3}, {%4,%5,%6,%7}, {%8,%9}, {%0,%1,%2,%3};"
        : "+f"(c[0]), "+f"(c[1]), "+f"(c[2]), "+f"(c[3])
        : "r"(a[0]), "r"(a[1]), "r"(a[2]), "r"(a[3]), "r"(b0), "r"(b1));
}
__device__ __forceinline__ uint32_t pack_f16x2(float even, float odd) {
    uint32_t r;
    asm("cvt.rn.f16x2.f32 %0, %1, %2;" : "=r"(r) : "f"(odd), "f"(even));
    return r;
}

// ---------------- graph bookkeeping -----------------------------------------
__global__ __launch_bounds__(256) void k_bookkeep(const int* __restrict__ b32)
{
    __shared__ int s_cnt[BG];
    __shared__ int s_any;
    int tid = threadIdx.x;

    if (tid == 0) s_any = 0;
    for (int i = tid; i < BG; i += 256) s_cnt[i] = 0;
    __syncthreads();

    int any = 0;
    for (int i = (NN / 2) + 1 + 2 * tid; i < NN; i += 2 * 256)
        if (b32[i] != 0) any = 1;
    if (any) atomicOr(&s_any, 1);
    __syncthreads();
    int is64 = (s_any == 0);

    for (int i = tid; i < NN; i += 256) {
        int v = is64 ? b32[2 * i] : b32[i];
        v = min(max(v, 0), BG - 1);
        atomicAdd(&s_cnt[v], 1);
    }
    __syncthreads();

    if (tid == 0) {
        int s = 0;
        for (int i = 0; i < BG; i++) {
            g_counts[i] = s_cnt[i];
            g_starts[i] = s;
            s += s_cnt[i];
        }
    }
}

// ---------------- weight conversion fp32 -> fp16 -----------------------------
__device__ __forceinline__ void conv_region(
    const float* __restrict__ src, __half* __restrict__ dst, size_t n,
    size_t gid, size_t stride)
{
    __half2* d2 = (__half2*)dst;
    const float2* s2 = (const float2*)src;
    for (size_t i = gid; i < n / 2; i += stride)
        d2[i] = __floats2half2_rn(s2[i].x, s2[i].y);
}

__global__ __launch_bounds__(256) void k_wconvert(
    const float* __restrict__ ipw, const float* __restrict__ ow,
    const float* __restrict__ f1w, const float* __restrict__ f2w)
{
    size_t gid = (size_t)blockIdx.x * 256 + threadIdx.x;
    size_t stride = (size_t)gridDim.x * 256;
    conv_region(ipw, g_w16 + IPW_OFF, 3 * (size_t)IPW_PER, gid, stride);
    conv_region(ow,  g_w16 + OW_OFF,  3 * (size_t)OW_PER,  gid, stride);
    conv_region(f1w, g_w16 + F1W_OFF, 3 * (size_t)F1W_PER, gid, stride);
    conv_region(f2w, g_w16 + F2W_OFF, 3 * (size_t)F2W_PER, gid, stride);
}

// ---------------- fp16 tensor GEMM: C = A[M,K] @ W[N,K]^T + bias ------------
// 128x128 tile, BK=32, cp.async double-buffer, ldmatrix fragments,
// 256 threads (8 warps 4x2), warp tile 32x64 (m16n8k16).
#define LDW 20                       // words per smem row (32 halves + pad)
#define TILE_W (128 * LDW)
#define TILE_B (TILE_W * 4)          // 10240 bytes
#define GEMM_SMEM (4 * TILE_B)       // 40960

__global__ void __launch_bounds__(256, 2) gemm_tc(
    int aid, int woff, const float* __restrict__ bias,
    int cid, int out16, int act, int M, int K, int Nout)
{
    extern __shared__ uint32_t dsm[];
    const __half* A = f16_ptr(aid);
    const __half* W = g_w16 + woff;

    const int tid  = threadIdx.x;
    const int warp = tid >> 5;
    const int lane = tid & 31;
    const int g    = lane >> 2;
    const int tig  = lane & 3;
    const int wm   = (warp >> 1) * 32;
    const int wn   = (warp & 1) * 64;
    const int m0 = blockIdx.y * 128;
    const int n0 = blockIdx.x * 128;

    const uint32_t sbase = smem_u32(dsm);

    // cp.async loader: thread covers chunks tid and tid+256 (16B = 8 halves)
    const int rowA = tid >> 2, chA = tid & 3;
    const int rowB = (tid + 256) >> 2, chB = tid & 3;   // (tid+256)&3 == tid&3
    const __half* Ag = A + (size_t)m0 * K;
    const __half* Wg = W + (size_t)n0 * K;
    const __half* AgA = Ag + (size_t)rowA * K + chA * 8;
    const __half* AgB = Ag + (size_t)rowB * K + chB * 8;
    const __half* WgA = Wg + (size_t)rowA * K + chA * 8;
    const __half* WgB = Wg + (size_t)rowB * K + chB * 8;
    const uint32_t sA = (rowA * LDW + chA * 4) * 4;
    const uint32_t sB = (rowB * LDW + chB * 4) * 4;

    // ldmatrix per-lane offsets
    const int grp = lane >> 3, l8 = lane & 7;
    const int rsel = (grp & 1) * 8, ksel = (grp >> 1) * 4;
    const uint32_t aoff0 = ((wm + 0  + rsel + l8) * LDW + ksel) * 4;
    const uint32_t aoff1 = ((wm + 16 + rsel + l8) * LDW + ksel) * 4;
    uint32_t boff[4];
    #pragma unroll
    for (int jp = 0; jp < 4; jp++)
        boff[jp] = ((wn + jp * 16 + rsel + l8) * LDW + ksel) * 4;

    float acc[2][8][4];
    #pragma unroll
    for (int i = 0; i < 2; i++)
        #pragma unroll
        for (int j = 0; j < 8; j++)
            #pragma unroll
            for (int r = 0; r < 4; r++) acc[i][j][r] = 0.f;

    const int S = K >> 5;

#define ISSUE(k0, buf)                                              \
    do {                                                            \
        uint32_t ab = sbase + (buf) * TILE_B;                       \
        uint32_t wb = sbase + 2 * TILE_B + (buf) * TILE_B;          \
        CPA16(ab + sA, AgA + (k0));                                 \
        CPA16(ab + sB, AgB + (k0));                                 \
        CPA16(wb + sA, WgA + (k0));                                 \
        CPA16(wb + sB, WgB + (k0));                                 \
        CPCOMMIT();                                                 \
    } while (0)

#define COMPUTE(buf)                                                         \
    do {                                                                     \
        uint32_t ab = sbase + (buf) * TILE_B;                                \
        uint32_t wb = sbase + 2 * TILE_B + (buf) * TILE_B;                   \
        _Pragma("unroll")                                                    \
        for (int ks = 0; ks < 2; ks++) {                                     \
            uint32_t kB = ks * 32;                                           \
            uint32_t af0[4], af1[4];                                         \
            LDMX4(af0[0], af0[1], af0[2], af0[3], ab + aoff0 + kB);          \
            LDMX4(af1[0], af1[1], af1[2], af1[3], ab + aoff1 + kB);          \
            _Pragma("unroll")                                                \
            for (int jp = 0; jp < 4; jp++) {                                 \
                uint32_t b0, b1, b2, b3;                                     \
                LDMX4(b0, b1, b2, b3, wb + boff[jp] + kB);                   \
                mma_f16(acc[0][2 * jp],     af0, b0, b2);                    \
                mma_f16(acc[0][2 * jp + 1], af0, b1, b3);                    \
                mma_f16(acc[1][2 * jp],     af1, b0, b2);                    \
                mma_f16(acc[1][2 * jp + 1], af1, b1, b3);                    \
            }                                                                \
        }                                                                    \
    } while (0)

    ISSUE(0, 0);
    for (int s = 0; s < S; s++) {
        int bf = s & 1;
        if (s + 1 < S) { ISSUE((s + 1) * 32, bf ^ 1); CPWAIT1(); }
        else           { CPWAIT0(); }
        __syncthreads();
        COMPUTE(bf);
        __syncthreads();
    }
#undef ISSUE
#undef COMPUTE

    // epilogue
    if (out16) {
        __half* C = f16_ptr(cid);
        #pragma unroll
        for (int j = 0; j < 8; j++) {
            int col = n0 + wn + j * 8 + 2 * tig;
            float2 bv = *(const float2*)(bias + col);
            #pragma unroll
            for (int i = 0; i < 2; i++) {
                int row0 = m0 + wm + i * 16 + g;
                float v0 = acc[i][j][0] + bv.x;
                float v1 = acc[i][j][1] + bv.y;
                float v2 = acc[i][j][2] + bv.x;
                float v3 = acc[i][j][3] + bv.y;
                if (act) {
                    v0 = fmaxf(v0, 0.f); v1 = fmaxf(v1, 0.f);
                    v2 = fmaxf(v2, 0.f); v3 = fmaxf(v3, 0.f);
                }
                *(uint32_t*)(C + (size_t)row0 * Nout + col)       = pack_f16x2(v0, v1);
                *(uint32_t*)(C + (size_t)(row0 + 8) * Nout + col) = pack_f16x2(v2, v3);
            }
        }
    } else {
        float* C = buf_ptr(cid);
        #pragma unroll
        for (int j = 0; j < 8; j++) {
            int col = n0 + wn + j * 8 + 2 * tig;
            float2 bv = *(const float2*)(bias + col);
            #pragma unroll
            for (int i = 0; i < 2; i++) {
                int row0 = m0 + wm + i * 16 + g;
                float v0 = acc[i][j][0] + bv.x;
                float v1 = acc[i][j][1] + bv.y;
                float v2 = acc[i][j][2] + bv.x;
                float v3 = acc[i][j][3] + bv.y;
                if (act) {
                    v0 = fmaxf(v0, 0.f); v1 = fmaxf(v1, 0.f);
                    v2 = fmaxf(v2, 0.f); v3 = fmaxf(v3, 0.f);
                }
                *(float2*)(C + (size_t)row0 * Nout + col)       = make_float2(v0, v1);
                *(float2*)(C + (size_t)(row0 + 8) * Nout + col) = make_float2(v2, v3);
            }
        }
    }
}

// ---------------- fp32 SIMT GEMM (embedding: K=92) + f16 copy ---------------
__global__ __launch_bounds__(256) void gemm_f32(
    const float* __restrict__ Aext,
    const float* __restrict__ W, const float* __restrict__ bias,
    int M, int K, int Nout)
{
    __shared__ __align__(16) float As[2][16][132];
    __shared__ __align__(16) float Ws[2][16][132];

    const float* A = Aext;

    const int tid = threadIdx.x;
    const int tx = tid & 15;
    const int ty = tid >> 4;
    const int m0 = blockIdx.y * 128;
    const int n0 = blockIdx.x * 128;

    const int lr = tid >> 2;
    const int lc = (tid & 3) * 4;

    const float* Ap0 = A + (size_t)(m0 + lr) * K;
    const float* Ap1 = A + (size_t)(m0 + lr + 64) * K;
    const float* Wp0 = W + (size_t)(n0 + lr) * K;
    const float* Wp1 = W + (size_t)(n0 + lr + 64) * K;

    float acc[8][8];
    #pragma unroll
    for (int i = 0; i < 8; i++)
        #pragma unroll
        for (int j = 0; j < 8; j++) acc[i][j] = 0.f;

    float4 ra0, ra1, rw0, rw1;
    const int ktiles = (K + 15) >> 4;

#define GLOAD(k0)                                                            \
    do {                                                                     \
        float* p0 = (float*)&ra0; float* p1 = (float*)&ra1;                  \
        float* q0 = (float*)&rw0; float* q1 = (float*)&rw1;                  \
        _Pragma("unroll")                                                    \
        for (int i = 0; i < 4; i++) {                                        \
            int kg = (k0) + lc + i;                                          \
            bool ok = (kg < K);                                              \
            p0[i] = ok ? Ap0[kg] : 0.f;                                      \
            p1[i] = ok ? Ap1[kg] : 0.f;                                      \
            q0[i] = ok ? Wp0[kg] : 0.f;                                      \
            q1[i] = ok ? Wp1[kg] : 0.f;                                      \
        }                                                                    \
    } while (0)

#define SSTORE(bf)                                                           \
    do {                                                                     \
        As[bf][lc + 0][lr]      = ra0.x; As[bf][lc + 1][lr]      = ra0.y;    \
        As[bf][lc + 2][lr]      = ra0.z; As[bf][lc + 3][lr]      = ra0.w;    \
        As[bf][lc + 0][lr + 64] = ra1.x; As[bf][lc + 1][lr + 64] = ra1.y;    \
        As[bf][lc + 2][lr + 64] = ra1.z; As[bf][lc + 3][lr + 64] = ra1.w;    \
        Ws[bf][lc + 0][lr]      = rw0.x; Ws[bf][lc + 1][lr]      = rw0.y;    \
        Ws[bf][lc + 2][lr]      = rw0.z; Ws[bf][lc + 3][lr]      = rw0.w;    \
        Ws[bf][lc + 0][lr + 64] = rw1.x; Ws[bf][lc + 1][lr + 64] = rw1.y;    \
        Ws[bf][lc + 2][lr + 64] = rw1.z; Ws[bf][lc + 3][lr + 64] = rw1.w;    \
    } while (0)

#define COMPUTE(bf)                                                          \
    do {                                                                     \
        _Pragma("unroll")                                                    \
        for (int k = 0; k < 16; k++) {                                       \
            float4 a0 = *(const float4*)(&As[bf][k][ty * 8]);                \
            float4 a1 = *(const float4*)(&As[bf][k][ty * 8 + 4]);            \
            float4 b0 = *(const float4*)(&Ws[bf][k][tx * 8]);                \
            float4 b1 = *(const float4*)(&Ws[bf][k][tx * 8 + 4]);            \
            float ar[8] = {a0.x, a0.y, a0.z, a0.w, a1.x, a1.y, a1.z, a1.w};  \
            float br[8] = {b0.x, b0.y, b0.z, b0.w, b1.x, b1.y, b1.z, b1.w};  \
            _Pragma("unroll")                                                \
            for (int i = 0; i < 8; i++)                                      \
                _Pragma("unroll")                                            \
                for (int j = 0; j < 8; j++)                                  \
                    acc[i][j] = fmaf(ar[i], br[j], acc[i][j]);               \
        }                                                                    \
    } while (0)

    GLOAD(0);
    SSTORE(0);
    __syncthreads();

    for (int kt = 0; kt < ktiles; kt++) {
        int bf = kt & 1;
        if (kt + 1 < ktiles) GLOAD((kt + 1) * 16);
        COMPUTE(bf);
        if (kt + 1 < ktiles) {
            SSTORE(bf ^ 1);
            __syncthreads();
        }
    }
#undef GLOAD
#undef SSTORE
#undef COMPUTE

    float4 bia0 = *(const float4*)(bias + n0 + tx * 8);
    float4 bia1 = *(const float4*)(bias + n0 + tx * 8 + 4);
    float bb[8] = {bia0.x, bia0.y, bia0.z, bia0.w, bia1.x, bia1.y, bia1.z, bia1.w};

    #pragma unroll
    for (int i = 0; i < 8; i++) {
        int m = m0 + ty * 8 + i;
        float*  Crow = g_h   + (size_t)m * Nout + n0 + tx * 8;
        __half* Hrow = g_h16 + (size_t)m * Nout + n0 + tx * 8;
        float r[8];
        #pragma unroll
        for (int j = 0; j < 8; j++) r[j] = acc[i][j] + bb[j];
        *(float4*)(Crow)     = make_float4(r[0], r[1], r[2], r[3]);
        *(float4*)(Crow + 4) = make_float4(r[4], r[5], r[6], r[7]);
        #pragma unroll
        for (int j = 0; j < 4; j++)
            *(uint32_t*)(Hrow + 2 * j) = pack_f16x2(r[2 * j], r[2 * j + 1]);
    }
}

// ---------------- ragged per-graph flash attention (f16 out) -----------------
__global__ __launch_bounds__(256) void attn_kernel()
{
    int b  = blockIdx.x;
    int h  = blockIdx.y;
    int qt = blockIdx.z;
    int cnt = g_counts[b];
    int q0  = qt * 32;
    if (q0 >= cnt) return;
    int start = g_starts[b];
    int nq = min(32, cnt - q0);

    __shared__ float Qs[32][65];
    __shared__ float Ks[32][65];
    __shared__ float Vs[32][65];
    __shared__ float Sc[32][33];

    int tid = threadIdx.x;

    for (int idx = tid; idx < 32 * 64; idx += 256) {
        int r = idx >> 6, d = idx & 63;
        Qs[r][d] = (r < nq)
            ? g_qkv[(size_t)(start + q0 + r) * (3 * DM) + h * HD + d] : 0.f;
    }

    int q  = tid >> 3;
    int dg = tid & 7;
    int d0 = dg * 8;

    float acc[8];
    #pragma unroll
    for (int i = 0; i < 8; i++) acc[i] = 0.f;
    float mloc = -INFINITY, lloc = 0.f;
    const float scale = 0.125f;

    for (int k0 = 0; k0 < cnt; k0 += 32) {
        int nk = min(32, cnt - k0);
        __syncthreads();
        for (int idx = tid; idx < 32 * 64; idx += 256) {
            int r = idx >> 6, d = idx & 63;
            if (r < nk) {
                size_t base = (size_t)(start + k0 + r) * (3 * DM) + h * HD + d;
                Ks[r][d] = g_qkv[base + DM];
                Vs[r][d] = g_qkv[base + 2 * DM];
            }
        }
        __syncthreads();

        float s[4] = {0.f, 0.f, 0.f, 0.f};
        for (int d = 0; d < 64; d++) {
            float qv = Qs[q][d];
            #pragma unroll
            for (int kk = 0; kk < 4; kk++)
                s[kk] = fmaf(qv, Ks[dg * 4 + kk][d], s[kk]);
        }
        #pragma unroll
        for (int kk = 0; kk < 4; kk++) {
            int k = dg * 4 + kk;
            Sc[q][k] = (k < nk) ? s[kk] * scale : -INFINITY;
        }
        __syncthreads();

        float mc = -INFINITY;
        #pragma unroll
        for (int k = 0; k < 32; k++) mc = fmaxf(mc, Sc[q][k]);
        float mnew = fmaxf(mloc, mc);
        float corr = (mloc == -INFINITY) ? 0.f : __expf(mloc - mnew);
        lloc *= corr;
        #pragma unroll
        for (int i = 0; i < 8; i++) acc[i] *= corr;
        for (int k = 0; k < nk; k++) {
            float p = __expf(Sc[q][k] - mnew);
            lloc += p;
            #pragma unroll
            for (int i = 0; i < 8; i++)
                acc[i] = fmaf(p, Vs[k][d0 + i], acc[i]);
        }
        mloc = mnew;
        __syncthreads();
    }

    if (q < nq) {
        float inv = 1.f / lloc;
        __half* o = g_t16 + (size_t)(start + q0 + q) * DM + h * HD + d0;
        #pragma unroll
        for (int i = 0; i < 4; i++)
            *(uint32_t*)(o + 2 * i) = pack_f16x2(acc[2 * i] * inv, acc[2 * i + 1] * inv);
    }
}

// ---------------- residual + layernorm (f32 out + optional f16 out) ----------
__global__ __launch_bounds__(128) void ln_kernel(
    int rid, int did, int oid, int oid16,
    const float* __restrict__ gg, const float* __restrict__ bb)
{
    const float* resid = buf_ptr(rid);
    const float* delta = buf_ptr(did);
    float*       out   = buf_ptr(oid);
    __half*      out16 = f16_ptr(oid16);

    int row = blockIdx.x;
    int tid = threadIdx.x;
    size_t base = (size_t)row * DM;

    float v[4];
    float s = 0.f, sq = 0.f;
    #pragma unroll
    for (int i = 0; i < 4; i++) {
        int c = tid + i * 128;
        float x = resid[base + c] + delta[base + c];
        v[i] = x;
        s += x; sq += x * x;
    }
    __shared__ float shs[4], shq[4];
    #pragma unroll
    for (int o = 16; o > 0; o >>= 1) {
        s  += __shfl_down_sync(0xffffffffu, s, o);
        sq += __shfl_down_sync(0xffffffffu, sq, o);
    }
    int w = tid >> 5;
    if ((tid & 31) == 0) { shs[w] = s; shq[w] = sq; }
    __syncthreads();
    float ts = shs[0] + shs[1] + shs[2] + shs[3];
    float tq = shq[0] + shq[1] + shq[2] + shq[3];
    float mean = ts * (1.f / DM);
    float var  = tq * (1.f / DM) - mean * mean;
    float inv  = rsqrtf(fmaxf(var, 0.f) + LN_EPS);
    #pragma unroll
    for (int i = 0; i < 4; i++) {
        int c = tid + i * 128;
        float r = (v[i] - mean) * inv * gg[c] + bb[c];
        out[base + c] = r;
        out16[base + c] = __float2half(r);
    }
}

// ---------------- segment mean pool -----------------------------------------
__global__ __launch_bounds__(256) void pool_kernel()
{
    int b = blockIdx.x;
    int tid = threadIdx.x;
    int cnt = g_counts[b], st = g_starts[b];
    float a0 = 0.f, a1 = 0.f;
    for (int r = 0; r < cnt; r++) {
        size_t base = (size_t)(st + r) * DM;
        a0 += g_h[base + tid];
        a1 += g_h[base + tid + 256];
    }
    float inv = (cnt > 0) ? 1.f / (float)cnt : 0.f;
    g_pooled[b * DM + tid]       = a0 * inv;
    g_pooled[b * DM + tid + 256] = a1 * inv;
}

// ---------------- head ------------------------------------------------------
__global__ __launch_bounds__(256) void head_kernel(
    const float* __restrict__ w1, const float* __restrict__ b1,
    const float* __restrict__ w2, const float* __restrict__ b2,
    float* __restrict__ out)
{
    int b = blockIdx.x;
    int tid = threadIdx.x;
    __shared__ float ps[DM];
    ps[tid]       = g_pooled[b * DM + tid];
    ps[tid + 256] = g_pooled[b * DM + tid + 256];
    __syncthreads();

    int warp = tid >> 5, lane = tid & 31;
    float partial = 0.f;
    for (int j = warp; j < DM; j += 8) {
        float a = 0.f;
        const float* wr = w1 + (size_t)j * DM;
        for (int k = lane; k < DM; k += 32) a = fmaf(ps[k], wr[k], a);
        #pragma unroll
        for (int o = 16; o > 0; o >>= 1) a += __shfl_down_sync(0xffffffffu, a, o);
        if (lane == 0) {
            a += b1[j];
            float sil = a / (1.f + __expf(-a));
            partial = fmaf(sil, w2[j], partial);
        }
    }
    __shared__ float red[8];
    if (lane == 0) red[warp] = partial;
    __syncthreads();
    if (tid == 0) {
        float t = 0.f;
        #pragma unroll
        for (int i = 0; i < 8; i++) t += red[i];
        out[b] = t + b2[0];
    }
}

// ---------------- launch -----------------------------------------------------
extern "C" void kernel_launch(void* const* d_in, const int* in_sizes, int n_in,
                              void* d_out, int out_size)
{
    const float* node_features = (const float*)d_in[0];
    const int*   batch32       = (const int*)d_in[3];
    const float* emb_w    = (const float*)d_in[4];
    const float* emb_b    = (const float*)d_in[5];
    const float* in_proj_w = (const float*)d_in[6];
    const float* in_proj_b = (const float*)d_in[7];
    const float* out_w    = (const float*)d_in[8];
    const float* out_b    = (const float*)d_in[9];
    const float* ln1_g    = (const float*)d_in[10];
    const float* ln1_b    = (const float*)d_in[11];
    const float* ffn_w1   = (const float*)d_in[12];
    const float* ffn_b1   = (const float*)d_in[13];
    const float* ffn_w2   = (const float*)d_in[14];
    const float* ffn_b2   = (const float*)d_in[15];
    const float* ln2_g    = (const float*)d_in[16];
    const float* ln2_b    = (const float*)d_in[17];
    const float* head_w1  = (const float*)d_in[18];
    const float* head_b1  = (const float*)d_in[19];
    const float* head_w2  = (const float*)d_in[20];
    const float* head_b2  = (const float*)d_in[21];
    float* out = (float*)d_out;

    cudaFuncSetAttribute(gemm_tc, cudaFuncAttributeMaxDynamicSharedMemorySize,
                         GEMM_SMEM);

    k_bookkeep<<<1, 256>>>(batch32);
    k_wconvert<<<2048, 256>>>(in_proj_w, out_w, ffn_w1, ffn_w2);

    // embedding (fp32, K=92) -> g_h + g_h16
    gemm_f32<<<dim3(DM / 128, NN / 128), 256>>>(
        node_features, emb_w, emb_b, NN, DIN, DM);

    for (int l = 0; l < NL; l++) {
        const float* ipb = in_proj_b + (size_t)l * 3 * DM;
        const float* ob  = out_b + (size_t)l * DM;
        const float* f1b = ffn_b1 + (size_t)l * DFF;
        const float* f2b = ffn_b2 + (size_t)l * DM;

        // qkv = h16 @ ipw^T -> g_qkv (f32)
        gemm_tc<<<dim3(3 * DM / 128, NN / 128), 256, GEMM_SMEM>>>(
            F16_H, IPW_OFF + l * IPW_PER, ipb, BUF_QKV, 0, 0, NN, DM, 3 * DM);

        // attention -> g_t16
        attn_kernel<<<dim3(BG, NH, 16), 256>>>();

        // o proj = t16 @ ow^T -> g_x (f32)
        gemm_tc<<<dim3(DM / 128, NN / 128), 256, GEMM_SMEM>>>(
            F16_T, OW_OFF + l * OW_PER, ob, BUF_X, 0, 0, NN, DM, DM);

        // x = LN(h + o) -> g_x (f32) + g_x16
        ln_kernel<<<NN, 128>>>(BUF_H, BUF_X, BUF_X, F16_X,
                               ln1_g + (size_t)l * DM, ln1_b + (size_t)l * DM);

        // ffn1 = relu(x16 @ f1w^T) -> g_f16 (f16 only)
        gemm_tc<<<dim3(DFF / 128, NN / 128), 256, GEMM_SMEM>>>(
            F16_X, F1W_OFF + l * F1W_PER, f1b, F16_F, 1, 1, NN, DM, DFF);

        // ffn2 = f16 @ f2w^T -> g_qkv (f32 scratch)
        gemm_tc<<<dim3(DM / 128, NN / 128), 256, GEMM_SMEM>>>(
            F16_F, F2W_OFF + l * F2W_PER, f2b, BUF_QKV, 0, 0, NN, DFF, DM);

        // h = LN(x + ffn2) -> g_h (f32) + g_h16
        ln_kernel<<<NN, 128>>>(BUF_X, BUF_QKV, BUF_H, F16_H,
                               ln2_g + (size_t)l * DM, ln2_b + (size_t)l * DM);
    }

    pool_kernel<<<BG, 256>>>();
    head_kernel<<<BG, 256>>>(head_w1, head_b1, head_w2, head_b2, out);
}

// round 14
// speedup vs baseline: 6.8083x; 1.0760x over previous
#include <cuda_runtime.h>
#include <cuda_fp16.h>
#include <math.h>
#include <stdint.h>

#define NN   24576
#define DIN  92
#define DM   512
#define NH   8
#define HD   64
#define NL   3
#define DFF  2048
#define BG   128
#define LN_EPS 1e-5f

// ---------------- scratch (static device globals; no allocs allowed) --------
__device__ float g_h[(size_t)NN * DM];          // f32 hidden (residual/pool)
__device__ float g_qkv[(size_t)NN * 3 * DM];    // f32 ffn2-out scratch
__device__ float g_x[(size_t)NN * DM];          // f32 post-LN1
__device__ float g_pooled[BG * DM];
__device__ int   g_counts[BG];
__device__ int   g_starts[BG];

__device__ __half g_h16[(size_t)NN * DM];       // f16 of hidden
__device__ __half g_x16[(size_t)NN * DM];       // f16 of post-LN1
__device__ __half g_t16[(size_t)NN * DM];       // f16 attn out
__device__ __half g_f16[(size_t)NN * DFF];      // f16 ffn hidden
__device__ __half g_qkv16[(size_t)NN * 3 * DM]; // f16 qkv
__device__ __half g_w16[9437184];               // f16 weights (all layers)

// f32 buffer ids
#define BUF_H    0
#define BUF_QKV  1
#define BUF_X    2
__device__ __forceinline__ float* buf_ptr(int id) {
    switch (id) {
        case BUF_H:   return g_h;
        case BUF_QKV: return g_qkv;
        default:      return g_x;
    }
}
// f16 buffer ids
#define F16_H    0
#define F16_X    1
#define F16_T    2
#define F16_F    3
#define F16_QKV  4
__device__ __forceinline__ __half* f16_ptr(int id) {
    switch (id) {
        case F16_H: return g_h16;
        case F16_X: return g_x16;
        case F16_T: return g_t16;
        case F16_F: return g_f16;
        default:    return g_qkv16;
    }
}

// weight offsets in g_w16 (halves)
#define IPW_OFF 0
#define IPW_PER (3 * DM * DM)
#define OW_OFF  (3 * IPW_PER)
#define OW_PER  (DM * DM)
#define F1W_OFF (OW_OFF + 3 * OW_PER)
#define F1W_PER (DFF * DM)
#define F2W_OFF (F1W_OFF + 3 * F1W_PER)
#define F2W_PER (DM * DFF)

// ---------------- PTX helpers ------------------------------------------------
__device__ __forceinline__ uint32_t smem_u32(const void* p) {
    uint32_t a;
    asm("{ .reg .u64 t; cvta.to.shared.u64 t, %1; cvt.u32.u64 %0, t; }"
        : "=r"(a) : "l"(p));
    return a;
}
#define CPA16(dst, src) \
    asm volatile("cp.async.ca.shared.global [%0], [%1], 16;" :: "r"(dst), "l"(src))
#define CPCOMMIT() asm volatile("cp.async.commit_group;" ::: "memory")
#define CPWAIT1()  asm volatile("cp.async.wait_group 1;" ::: "memory")
#define CPWAIT0()  asm volatile("cp.async.wait_group 0;" ::: "memory")
#define LDMX4(r0, r1, r2, r3, a) \
    asm volatile("ldmatrix.sync.aligned.m8n8.x4.shared.b16 {%0,%1,%2,%3}, [%4];" \
                 : "=r"(r0), "=r"(r1), "=r"(r2), "=r"(r3) : "r"(a))

__device__ __forceinline__ void mma_f16(float* c, const uint32_t* a,
                                        uint32_t b0, uint32_t b1) {
    asm volatile(
        "mma.sync.aligned.m16n8k16.row.col.f32.f16.f16.f32 "
        "{%0,%1,%2,%3}, {%4,%5,%6,%7}, {%8,%9}, {%0,%1,%2,%3};"
        : "+f"(c[0]), "+f"(c[1]), "+f"(c[2]), "+f"(c[3])
        : "r"(a[0]), "r"(a[1]), "r"(a[2]), "r"(a[3]), "r"(b0), "r"(b1));
}
__device__ __forceinline__ uint32_t pack_f16x2(float even, float odd) {
    uint32_t r;
    asm("cvt.rn.f16x2.f32 %0, %1, %2;" : "=r"(r) : "f"(odd), "f"(even));
    return r;
}

// ---------------- graph bookkeeping -----------------------------------------
__global__ __launch_bounds__(256) void k_bookkeep(const int* __restrict__ b32)
{
    __shared__ int s_cnt[BG];
    __shared__ int s_any;
    int tid = threadIdx.x;

    if (tid == 0) s_any = 0;
    for (int i = tid; i < BG; i += 256) s_cnt[i] = 0;
    __syncthreads();

    int any = 0;
    for (int i = (NN / 2) + 1 + 2 * tid; i < NN; i += 2 * 256)
        if (b32[i] != 0) any = 1;
    if (any) atomicOr(&s_any, 1);
    __syncthreads();
    int is64 = (s_any == 0);

    for (int i = tid; i < NN; i += 256) {
        int v = is64 ? b32[2 * i] : b32[i];
        v = min(max(v, 0), BG - 1);
        atomicAdd(&s_cnt[v], 1);
    }
    __syncthreads();

    if (tid == 0) {
        int s = 0;
        for (int i = 0; i < BG; i++) {
            g_counts[i] = s_cnt[i];
            g_starts[i] = s;
            s += s_cnt[i];
        }
    }
}

// ---------------- weight conversion fp32 -> fp16 -----------------------------
__device__ __forceinline__ void conv_region(
    const float* __restrict__ src, __half* __restrict__ dst, size_t n,
    size_t gid, size_t stride)
{
    __half2* d2 = (__half2*)dst;
    const float2* s2 = (const float2*)src;
    for (size_t i = gid; i < n / 2; i += stride)
        d2[i] = __floats2half2_rn(s2[i].x, s2[i].y);
}

__global__ __launch_bounds__(256) void k_wconvert(
    const float* __restrict__ ipw, const float* __restrict__ ow,
    const float* __restrict__ f1w, const float* __restrict__ f2w)
{
    size_t gid = (size_t)blockIdx.x * 256 + threadIdx.x;
    size_t stride = (size_t)gridDim.x * 256;
    conv_region(ipw, g_w16 + IPW_OFF, 3 * (size_t)IPW_PER, gid, stride);
    conv_region(ow,  g_w16 + OW_OFF,  3 * (size_t)OW_PER,  gid, stride);
    conv_region(f1w, g_w16 + F1W_OFF, 3 * (size_t)F1W_PER, gid, stride);
    conv_region(f2w, g_w16 + F2W_OFF, 3 * (size_t)F2W_PER, gid, stride);
}

// ---------------- fp16 tensor GEMM: C = A[M,K] @ W[N,K]^T + bias ------------
// 128x128 tile, BK=32, 3-stage cp.async pipeline (1 sync/stage),
// ldmatrix fragments, 256 threads (8 warps 4x2), warp tile 32x64.
#define LDW 20                       // words per smem row (32 halves + pad)
#define TILE_W (128 * LDW)
#define TILE_B (TILE_W * 4)          // 10240 bytes
#define GEMM_SMEM (6 * TILE_B)       // 3 stages x (A+W) = 61440

__global__ void __launch_bounds__(256, 2) gemm_tc(
    int aid, int woff, const float* __restrict__ bias,
    int cid, int out16, int act, int M, int K, int Nout)
{
    extern __shared__ uint32_t dsm[];
    const __half* A = f16_ptr(aid);
    const __half* W = g_w16 + woff;

    const int tid  = threadIdx.x;
    const int warp = tid >> 5;
    const int lane = tid & 31;
    const int g    = lane >> 2;
    const int tig  = lane & 3;
    const int wm   = (warp >> 1) * 32;
    const int wn   = (warp & 1) * 64;
    const int m0 = blockIdx.y * 128;
    const int n0 = blockIdx.x * 128;

    const uint32_t sbase = smem_u32(dsm);

    const int rowA = tid >> 2, chA = tid & 3;
    const int rowB = (tid + 256) >> 2;
    const __half* Ag = A + (size_t)m0 * K;
    const __half* Wg = W + (size_t)n0 * K;
    const __half* AgA = Ag + (size_t)rowA * K + chA * 8;
    const __half* AgB = Ag + (size_t)rowB * K + chA * 8;
    const __half* WgA = Wg + (size_t)rowA * K + chA * 8;
    const __half* WgB = Wg + (size_t)rowB * K + chA * 8;
    const uint32_t sA = (rowA * LDW + chA * 4) * 4;
    const uint32_t sB = (rowB * LDW + chA * 4) * 4;

    const int grp = lane >> 3, l8 = lane & 7;
    const int rsel = (grp & 1) * 8, ksel = (grp >> 1) * 4;
    const uint32_t aoff0 = ((wm + 0  + rsel + l8) * LDW + ksel) * 4;
    const uint32_t aoff1 = ((wm + 16 + rsel + l8) * LDW + ksel) * 4;
    uint32_t boff[4];
    #pragma unroll
    for (int jp = 0; jp < 4; jp++)
        boff[jp] = ((wn + jp * 16 + rsel + l8) * LDW + ksel) * 4;

    float acc[2][8][4];
    #pragma unroll
    for (int i = 0; i < 2; i++)
        #pragma unroll
        for (int j = 0; j < 8; j++)
            #pragma unroll
            for (int r = 0; r < 4; r++) acc[i][j][r] = 0.f;

    const int S = K >> 5;

#define ISSUE(k0, buf)                                              \
    do {                                                            \
        uint32_t ab = sbase + (buf) * TILE_B;                       \
        uint32_t wb = sbase + 3 * TILE_B + (buf) * TILE_B;          \
        CPA16(ab + sA, AgA + (k0));                                 \
        CPA16(ab + sB, AgB + (k0));                                 \
        CPA16(wb + sA, WgA + (k0));                                 \
        CPA16(wb + sB, WgB + (k0));                                 \
        CPCOMMIT();                                                 \
    } while (0)

#define COMPUTE(buf)                                                         \
    do {                                                                     \
        uint32_t ab = sbase + (buf) * TILE_B;                                \
        uint32_t wb = sbase + 3 * TILE_B + (buf) * TILE_B;                   \
        _Pragma("unroll")                                                    \
        for (int ks = 0; ks < 2; ks++) {                                     \
            uint32_t kB = ks * 32;                                           \
            uint32_t af0[4], af1[4];                                         \
            LDMX4(af0[0], af0[1], af0[2], af0[3], ab + aoff0 + kB);          \
            LDMX4(af1[0], af1[1], af1[2], af1[3], ab + aoff1 + kB);          \
            _Pragma("unroll")                                                \
            for (int jp = 0; jp < 4; jp++) {                                 \
                uint32_t b0, b1, b2, b3;                                     \
                LDMX4(b0, b1, b2, b3, wb + boff[jp] + kB);                   \
                mma_f16(acc[0][2 * jp],     af0, b0, b2);                    \
                mma_f16(acc[0][2 * jp + 1], af0, b1, b3);                    \
                mma_f16(acc[1][2 * jp],     af1, b0, b2);                    \
                mma_f16(acc[1][2 * jp + 1], af1, b1, b3);                    \
            }                                                                \
        }                                                                    \
    } while (0)

    ISSUE(0, 0);
    ISSUE(32, 1);
    for (int s = 0; s < S; s++) {
        if (s == S - 1) CPWAIT0(); else CPWAIT1();
        __syncthreads();
        if (s + 2 < S) ISSUE((s + 2) * 32, (s + 2) % 3);
        COMPUTE(s % 3);
    }
#undef ISSUE
#undef COMPUTE

    // epilogue
    if (out16) {
        __half* C = f16_ptr(cid);
        #pragma unroll
        for (int j = 0; j < 8; j++) {
            int col = n0 + wn + j * 8 + 2 * tig;
            float2 bv = *(const float2*)(bias + col);
            #pragma unroll
            for (int i = 0; i < 2; i++) {
                int row0 = m0 + wm + i * 16 + g;
                float v0 = acc[i][j][0] + bv.x;
                float v1 = acc[i][j][1] + bv.y;
                float v2 = acc[i][j][2] + bv.x;
                float v3 = acc[i][j][3] + bv.y;
                if (act) {
                    v0 = fmaxf(v0, 0.f); v1 = fmaxf(v1, 0.f);
                    v2 = fmaxf(v2, 0.f); v3 = fmaxf(v3, 0.f);
                }
                *(uint32_t*)(C + (size_t)row0 * Nout + col)       = pack_f16x2(v0, v1);
                *(uint32_t*)(C + (size_t)(row0 + 8) * Nout + col) = pack_f16x2(v2, v3);
            }
        }
    } else {
        float* C = buf_ptr(cid);
        #pragma unroll
        for (int j = 0; j < 8; j++) {
            int col = n0 + wn + j * 8 + 2 * tig;
            float2 bv = *(const float2*)(bias + col);
            #pragma unroll
            for (int i = 0; i < 2; i++) {
                int row0 = m0 + wm + i * 16 + g;
                float v0 = acc[i][j][0] + bv.x;
                float v1 = acc[i][j][1] + bv.y;
                float v2 = acc[i][j][2] + bv.x;
                float v3 = acc[i][j][3] + bv.y;
                if (act) {
                    v0 = fmaxf(v0, 0.f); v1 = fmaxf(v1, 0.f);
                    v2 = fmaxf(v2, 0.f); v3 = fmaxf(v3, 0.f);
                }
                *(float2*)(C + (size_t)row0 * Nout + col)       = make_float2(v0, v1);
                *(float2*)(C + (size_t)(row0 + 8) * Nout + col) = make_float2(v2, v3);
            }
        }
    }
}

// ---------------- fp32 SIMT GEMM (embedding: K=92) + f16 copy ---------------
__global__ __launch_bounds__(256) void gemm_f32(
    const float* __restrict__ Aext,
    const float* __restrict__ W, const float* __restrict__ bias,
    int M, int K, int Nout)
{
    __shared__ __align__(16) float As[2][16][132];
    __shared__ __align__(16) float Ws[2][16][132];

    const float* A = Aext;

    const int tid = threadIdx.x;
    const int tx = tid & 15;
    const int ty = tid >> 4;
    const int m0 = blockIdx.y * 128;
    const int n0 = blockIdx.x * 128;

    const int lr = tid >> 2;
    const int lc = (tid & 3) * 4;

    const float* Ap0 = A + (size_t)(m0 + lr) * K;
    const float* Ap1 = A + (size_t)(m0 + lr + 64) * K;
    const float* Wp0 = W + (size_t)(n0 + lr) * K;
    const float* Wp1 = W + (size_t)(n0 + lr + 64) * K;

    float acc[8][8];
    #pragma unroll
    for (int i = 0; i < 8; i++)
        #pragma unroll
        for (int j = 0; j < 8; j++) acc[i][j] = 0.f;

    float4 ra0, ra1, rw0, rw1;
    const int ktiles = (K + 15) >> 4;

#define GLOAD(k0)                                                            \
    do {                                                                     \
        float* p0 = (float*)&ra0; float* p1 = (float*)&ra1;                  \
        float* q0 = (float*)&rw0; float* q1 = (float*)&rw1;                  \
        _Pragma("unroll")                                                    \
        for (int i = 0; i < 4; i++) {                                        \
            int kg = (k0) + lc + i;                                          \
            bool ok = (kg < K);                                              \
            p0[i] = ok ? Ap0[kg] : 0.f;                                      \
            p1[i] = ok ? Ap1[kg] : 0.f;                                      \
            q0[i] = ok ? Wp0[kg] : 0.f;                                      \
            q1[i] = ok ? Wp1[kg] : 0.f;                                      \
        }                                                                    \
    } while (0)

#define SSTORE(bf)                                                           \
    do {                                                                     \
        As[bf][lc + 0][lr]      = ra0.x; As[bf][lc + 1][lr]      = ra0.y;    \
        As[bf][lc + 2][lr]      = ra0.z; As[bf][lc + 3][lr]      = ra0.w;    \
        As[bf][lc + 0][lr + 64] = ra1.x; As[bf][lc + 1][lr + 64] = ra1.y;    \
        As[bf][lc + 2][lr + 64] = ra1.z; As[bf][lc + 3][lr + 64] = ra1.w;    \
        Ws[bf][lc + 0][lr]      = rw0.x; Ws[bf][lc + 1][lr]      = rw0.y;    \
        Ws[bf][lc + 2][lr]      = rw0.z; Ws[bf][lc + 3][lr]      = rw0.w;    \
        Ws[bf][lc + 0][lr + 64] = rw1.x; Ws[bf][lc + 1][lr + 64] = rw1.y;    \
        Ws[bf][lc + 2][lr + 64] = rw1.z; Ws[bf][lc + 3][lr + 64] = rw1.w;    \
    } while (0)

#define COMPUTE(bf)                                                          \
    do {                                                                     \
        _Pragma("unroll")                                                    \
        for (int k = 0; k < 16; k++) {                                       \
            float4 a0 = *(const float4*)(&As[bf][k][ty * 8]);                \
            float4 a1 = *(const float4*)(&As[bf][k][ty * 8 + 4]);            \
            float4 b0 = *(const float4*)(&Ws[bf][k][tx * 8]);                \
            float4 b1 = *(const float4*)(&Ws[bf][k][tx * 8 + 4]);            \
            float ar[8] = {a0.x, a0.y, a0.z, a0.w, a1.x, a1.y, a1.z, a1.w};  \
            float br[8] = {b0.x, b0.y, b0.z, b0.w, b1.x, b1.y, b1.z, b1.w};  \
            _Pragma("unroll")                                                \
            for (int i = 0; i < 8; i++)                                      \
                _Pragma("unroll")                                            \
                for (int j = 0; j < 8; j++)                                  \
                    acc[i][j] = fmaf(ar[i], br[j], acc[i][j]);               \
        }                                                                    \
    } while (0)

    GLOAD(0);
    SSTORE(0);
    __syncthreads();

    for (int kt = 0; kt < ktiles; kt++) {
        int bf = kt & 1;
        if (kt + 1 < ktiles) GLOAD((kt + 1) * 16);
        COMPUTE(bf);
        if (kt + 1 < ktiles) {
            SSTORE(bf ^ 1);
            __syncthreads();
        }
    }
#undef GLOAD
#undef SSTORE
#undef COMPUTE

    float4 bia0 = *(const float4*)(bias + n0 + tx * 8);
    float4 bia1 = *(const float4*)(bias + n0 + tx * 8 + 4);
    float bb[8] = {bia0.x, bia0.y, bia0.z, bia0.w, bia1.x, bia1.y, bia1.z, bia1.w};

    #pragma unroll
    for (int i = 0; i < 8; i++) {
        int m = m0 + ty * 8 + i;
        float*  Crow = g_h   + (size_t)m * Nout + n0 + tx * 8;
        __half* Hrow = g_h16 + (size_t)m * Nout + n0 + tx * 8;
        float r[8];
        #pragma unroll
        for (int j = 0; j < 8; j++) r[j] = acc[i][j] + bb[j];
        *(float4*)(Crow)     = make_float4(r[0], r[1], r[2], r[3]);
        *(float4*)(Crow + 4) = make_float4(r[4], r[5], r[6], r[7]);
        #pragma unroll
        for (int j = 0; j < 4; j++)
            *(uint32_t*)(Hrow + 2 * j) = pack_f16x2(r[2 * j], r[2 * j + 1]);
    }
}

// ---------------- tensor-core ragged flash attention -------------------------
// 128 threads (4 warps), grid (BG, NH, 16 q-tiles of 32).
// S = Q@K^T and O = P@V via m16n8k16; softmax SIMT on 32x32 smem tile.
__global__ __launch_bounds__(128) void attn_kernel()
{
    int b  = blockIdx.x;
    int h  = blockIdx.y;
    int qt = blockIdx.z;
    int cnt = g_counts[b];
    int q0  = qt * 32;
    if (q0 >= cnt) return;
    int start = g_starts[b];
    int nq = min(32, cnt - q0);

    __shared__ __half Qs[32][72];    // 144B rows (36 words)
    __shared__ __half Ks[32][72];
    __shared__ __half Vs[64][40];    // transposed V: [d][kv], 80B rows
    __shared__ __half Ps[32][40];    // P tile, 80B rows
    __shared__ float  Sc[32][34];
    __shared__ float  s_m[32], s_l[32], s_corr[32];

    const int tid  = threadIdx.x;
    const int warp = tid >> 5;
    const int lane = tid & 31;
    const int grp = lane >> 3, l8 = lane & 7;
    const int rsel = (grp & 1) * 8;
    const int ksel16 = (grp >> 1) * 16;     // bytes
    const int qr = lane >> 2;               // 0..7 (C-frag row-in-8)
    const int qc = lane & 3;

    const uint32_t qb = smem_u32(&Qs[0][0]);
    const uint32_t kb = smem_u32(&Ks[0][0]);
    const uint32_t vb = smem_u32(&Vs[0][0]);
    const uint32_t pb = smem_u32(&Ps[0][0]);

    // load Q (zero-pad rows >= nq)
    {
        const __half* Qg = g_qkv16 + (size_t)(start + q0) * (3 * DM) + h * HD;
        #pragma unroll
        for (int c = tid; c < 256; c += 128) {
            int r = c >> 3, off = (c & 7) * 8;
            uint4 v = make_uint4(0, 0, 0, 0);
            if (r < nq) v = *(const uint4*)(Qg + (size_t)r * (3 * DM) + off);
            *(uint4*)(&Qs[r][off]) = v;
        }
    }
    if (tid < 32) { s_m[tid] = -INFINITY; s_l[tid] = 0.f; }

    float accO[2][2][4];
    #pragma unroll
    for (int i = 0; i < 2; i++)
        #pragma unroll
        for (int j = 0; j < 2; j++)
            #pragma unroll
            for (int r = 0; r < 4; r++) accO[i][j][r] = 0.f;

    const int mi = warp >> 1;    // S-MMA row half
    const int nj = warp & 1;     // S-MMA col half
    const float scale = 0.125f;

    int ktiles = (cnt + 31) >> 5;
    for (int kt = 0; kt < ktiles; kt++) {
        int k0 = kt * 32;
        int nk = min(32, cnt - k0);
        __syncthreads();   // Ks/Vs/Ps free (prev iteration fully consumed)

        // load K rows (garbage rows >= nk are masked later)
        const __half* Kg = g_qkv16 + (size_t)(start + k0) * (3 * DM) + DM + h * HD;
        #pragma unroll
        for (int c = tid; c < 256; c += 128) {
            int r = c >> 3, off = (c & 7) * 8;
            if (r < nk)
                *(uint4*)(&Ks[r][off]) = *(const uint4*)(Kg + (size_t)r * (3 * DM) + off);
        }
        // load V transposed: thread -> kv row (lane), d-chunk (warp)
        {
            const __half* Vg = g_qkv16 + (size_t)(start + k0) * (3 * DM) + 2 * DM + h * HD;
            int r = lane, dc = warp * 16;
            if (r < nk) {
                const __half* src = Vg + (size_t)r * (3 * DM) + dc;
                #pragma unroll
                for (int i = 0; i < 16; i++) Vs[dc + i][r] = src[i];
            } else {
                #pragma unroll
                for (int i = 0; i < 16; i++) Vs[dc + i][r] = __ushort_as_half(0);
            }
        }
        __syncthreads();

        // S-MMA: warp computes rows mi*16..+15, cols nj*16..+15
        float accS[2][4] = {{0.f, 0.f, 0.f, 0.f}, {0.f, 0.f, 0.f, 0.f}};
        #pragma unroll
        for (int kc = 0; kc < 4; kc++) {
            uint32_t a0, a1, a2, a3, b0, b1, b2, b3;
            LDMX4(a0, a1, a2, a3,
                  qb + (mi * 16 + rsel + l8) * 144 + kc * 32 + ksel16);
            LDMX4(b0, b1, b2, b3,
                  kb + (nj * 16 + rsel + l8) * 144 + kc * 32 + ksel16);
            uint32_t af[4] = {a0, a1, a2, a3};
            mma_f16(accS[0], af, b0, b2);
            mma_f16(accS[1], af, b1, b3);
        }
        // write Sc (scaled)
        {
            int r0 = mi * 16 + qr;
            #pragma unroll
            for (int jn = 0; jn < 2; jn++) {
                int c0 = nj * 16 + jn * 8 + 2 * qc;
                Sc[r0][c0]         = accS[jn][0] * scale;
                Sc[r0][c0 + 1]     = accS[jn][1] * scale;
                Sc[r0 + 8][c0]     = accS[jn][2] * scale;
                Sc[r0 + 8][c0 + 1] = accS[jn][3] * scale;
            }
        }
        __syncthreads();

        // softmax: thread t -> row q = t>>2, covers k = (t&3)*8 .. +7
        {
            int q = tid >> 2, s4 = tid & 3;
            float v[8];
            float mx = -INFINITY;
            #pragma unroll
            for (int i = 0; i < 8; i++) {
                int k = s4 * 8 + i;
                v[i] = (k < nk) ? Sc[q][k] : -INFINITY;
                mx = fmaxf(mx, v[i]);
            }
            mx = fmaxf(mx, __shfl_xor_sync(0xffffffffu, mx, 1));
            mx = fmaxf(mx, __shfl_xor_sync(0xffffffffu, mx, 2));
            float mold = s_m[q];
            float mnew = fmaxf(mold, mx);
            float sum = 0.f;
            float p[8];
            #pragma unroll
            for (int i = 0; i < 8; i++) {
                p[i] = __expf(v[i] - mnew);
                sum += p[i];
            }
            sum += __shfl_xor_sync(0xffffffffu, sum, 1);
            sum += __shfl_xor_sync(0xffffffffu, sum, 2);
            #pragma unroll
            for (int i = 0; i < 4; i++)
                *(uint32_t*)(&Ps[q][s4 * 8 + 2 * i]) = pack_f16x2(p[2 * i], p[2 * i + 1]);
            if (s4 == 0) {
                float corr = __expf(mold - mnew);
                s_m[q] = mnew;
                s_l[q] = s_l[q] * corr + sum;
                s_corr[q] = corr;
            }
        }
        __syncthreads();

        // rescale accO by corr, then O += P @ V
        {
            #pragma unroll
            for (int m2 = 0; m2 < 2; m2++) {
                float c0 = s_corr[m2 * 16 + qr];
                float c1 = s_corr[m2 * 16 + qr + 8];
                #pragma unroll
                for (int jn = 0; jn < 2; jn++) {
                    accO[m2][jn][0] *= c0; accO[m2][jn][1] *= c0;
                    accO[m2][jn][2] *= c1; accO[m2][jn][3] *= c1;
                }
            }
            #pragma unroll
            for (int kc = 0; kc < 2; kc++) {
                uint32_t b0, b1, b2, b3;
                LDMX4(b0, b1, b2, b3,
                      vb + (warp * 16 + rsel + l8) * 80 + kc * 32 + ksel16);
                #pragma unroll
                for (int m2 = 0; m2 < 2; m2++) {
                    uint32_t a0, a1, a2, a3;
                    LDMX4(a0, a1, a2, a3,
                          pb + (m2 * 16 + rsel + l8) * 80 + kc * 32 + ksel16);
                    uint32_t af[4] = {a0, a1, a2, a3};
                    mma_f16(accO[m2][0], af, b0, b2);
                    mma_f16(accO[m2][1], af, b1, b3);
                }
            }
        }
    }

    // output: warp covers cols warp*16 + jn*8 + 2*qc
    #pragma unroll
    for (int m2 = 0; m2 < 2; m2++) {
        int r = m2 * 16 + qr;
        int r2 = r + 8;
        float inv  = (r  < nq) ? 1.f / s_l[r]  : 0.f;
        float inv2 = (r2 < nq) ? 1.f / s_l[r2] : 0.f;
        #pragma unroll
        for (int jn = 0; jn < 2; jn++) {
            int col = h * HD + warp * 16 + jn * 8 + 2 * qc;
            if (r < nq)
                *(uint32_t*)(g_t16 + (size_t)(start + q0 + r) * DM + col) =
                    pack_f16x2(accO[m2][jn][0] * inv, accO[m2][jn][1] * inv);
            if (r2 < nq)
                *(uint32_t*)(g_t16 + (size_t)(start + q0 + r2) * DM + col) =
                    pack_f16x2(accO[m2][jn][2] * inv2, accO[m2][jn][3] * inv2);
        }
    }
}

// ---------------- residual + layernorm (f32 out + f16 out) -------------------
__global__ __launch_bounds__(128) void ln_kernel(
    int rid, int did, int oid, int oid16,
    const float* __restrict__ gg, const float* __restrict__ bb)
{
    const float* resid = buf_ptr(rid);
    const float* delta = buf_ptr(did);
    float*       out   = buf_ptr(oid);
    __half*      out16 = f16_ptr(oid16);

    int row = blockIdx.x;
    int tid = threadIdx.x;
    size_t base = (size_t)row * DM;

    float v[4];
    float s = 0.f, sq = 0.f;
    #pragma unroll
    for (int i = 0; i < 4; i++) {
        int c = tid + i * 128;
        float x = resid[base + c] + delta[base + c];
        v[i] = x;
        s += x; sq += x * x;
    }
    __shared__ float shs[4], shq[4];
    #pragma unroll
    for (int o = 16; o > 0; o >>= 1) {
        s  += __shfl_down_sync(0xffffffffu, s, o);
        sq += __shfl_down_sync(0xffffffffu, sq, o);
    }
    int w = tid >> 5;
    if ((tid & 31) == 0) { shs[w] = s; shq[w] = sq; }
    __syncthreads();
    float ts = shs[0] + shs[1] + shs[2] + shs[3];
    float tq = shq[0] + shq[1] + shq[2] + shq[3];
    float mean = ts * (1.f / DM);
    float var  = tq * (1.f / DM) - mean * mean;
    float inv  = rsqrtf(fmaxf(var, 0.f) + LN_EPS);
    #pragma unroll
    for (int i = 0; i < 4; i++) {
        int c = tid + i * 128;
        float r = (v[i] - mean) * inv * gg[c] + bb[c];
        out[base + c] = r;
        out16[base + c] = __float2half(r);
    }
}

// ---------------- segment mean pool -----------------------------------------
__global__ __launch_bounds__(256) void pool_kernel()
{
    int b = blockIdx.x;
    int tid = threadIdx.x;
    int cnt = g_counts[b], st = g_starts[b];
    float a0 = 0.f, a1 = 0.f;
    for (int r = 0; r < cnt; r++) {
        size_t base = (size_t)(st + r) * DM;
        a0 += g_h[base + tid];
        a1 += g_h[base + tid + 256];
    }
    float inv = (cnt > 0) ? 1.f / (float)cnt : 0.f;
    g_pooled[b * DM + tid]       = a0 * inv;
    g_pooled[b * DM + tid + 256] = a1 * inv;
}

// ---------------- head ------------------------------------------------------
__global__ __launch_bounds__(256) void head_kernel(
    const float* __restrict__ w1, const float* __restrict__ b1,
    const float* __restrict__ w2, const float* __restrict__ b2,
    float* __restrict__ out)
{
    int b = blockIdx.x;
    int tid = threadIdx.x;
    __shared__ float ps[DM];
    ps[tid]       = g_pooled[b * DM + tid];
    ps[tid + 256] = g_pooled[b * DM + tid + 256];
    __syncthreads();

    int warp = tid >> 5, lane = tid & 31;
    float partial = 0.f;
    for (int j = warp; j < DM; j += 8) {
        float a = 0.f;
        const float* wr = w1 + (size_t)j * DM;
        for (int k = lane; k < DM; k += 32) a = fmaf(ps[k], wr[k], a);
        #pragma unroll
        for (int o = 16; o > 0; o >>= 1) a += __shfl_down_sync(0xffffffffu, a, o);
        if (lane == 0) {
            a += b1[j];
            float sil = a / (1.f + __expf(-a));
            partial = fmaf(sil, w2[j], partial);
        }
    }
    __shared__ float red[8];
    if (lane == 0) red[warp] = partial;
    __syncthreads();
    if (tid == 0) {
        float t = 0.f;
        #pragma unroll
        for (int i = 0; i < 8; i++) t += red[i];
        out[b] = t + b2[0];
    }
}

// ---------------- launch -----------------------------------------------------
extern "C" void kernel_launch(void* const* d_in, const int* in_sizes, int n_in,
                              void* d_out, int out_size)
{
    const float* node_features = (const float*)d_in[0];
    const int*   batch32       = (const int*)d_in[3];
    const float* emb_w    = (const float*)d_in[4];
    const float* emb_b    = (const float*)d_in[5];
    const float* in_proj_w = (const float*)d_in[6];
    const float* in_proj_b = (const float*)d_in[7];
    const float* out_w    = (const float*)d_in[8];
    const float* out_b    = (const float*)d_in[9];
    const float* ln1_g    = (const float*)d_in[10];
    const float* ln1_b    = (const float*)d_in[11];
    const float* ffn_w1   = (const float*)d_in[12];
    const float* ffn_b1   = (const float*)d_in[13];
    const float* ffn_w2   = (const float*)d_in[14];
    const float* ffn_b2   = (const float*)d_in[15];
    const float* ln2_g    = (const float*)d_in[16];
    const float* ln2_b    = (const float*)d_in[17];
    const float* head_w1  = (const float*)d_in[18];
    const float* head_b1  = (const float*)d_in[19];
    const float* head_w2  = (const float*)d_in[20];
    const float* head_b2  = (const float*)d_in[21];
    float* out = (float*)d_out;

    cudaFuncSetAttribute(gemm_tc, cudaFuncAttributeMaxDynamicSharedMemorySize,
                         GEMM_SMEM);

    k_bookkeep<<<1, 256>>>(batch32);
    k_wconvert<<<2048, 256>>>(in_proj_w, out_w, ffn_w1, ffn_w2);

    // embedding (fp32, K=92) -> g_h + g_h16
    gemm_f32<<<dim3(DM / 128, NN / 128), 256>>>(
        node_features, emb_w, emb_b, NN, DIN, DM);

    for (int l = 0; l < NL; l++) {
        const float* ipb = in_proj_b + (size_t)l * 3 * DM;
        const float* ob  = out_b + (size_t)l * DM;
        const float* f1b = ffn_b1 + (size_t)l * DFF;
        const float* f2b = ffn_b2 + (size_t)l * DM;

        // qkv = h16 @ ipw^T -> g_qkv16 (f16)
        gemm_tc<<<dim3(3 * DM / 128, NN / 128), 256, GEMM_SMEM>>>(
            F16_H, IPW_OFF + l * IPW_PER, ipb, F16_QKV, 1, 0, NN, DM, 3 * DM);

        // tensor-core attention -> g_t16
        attn_kernel<<<dim3(BG, NH, 16), 128>>>();

        // o proj = t16 @ ow^T -> g_x (f32)
        gemm_tc<<<dim3(DM / 128, NN / 128), 256, GEMM_SMEM>>>(
            F16_T, OW_OFF + l * OW_PER, ob, BUF_X, 0, 0, NN, DM, DM);

        // x = LN(h + o) -> g_x (f32) + g_x16
        ln_kernel<<<NN, 128>>>(BUF_H, BUF_X, BUF_X, F16_X,
                               ln1_g + (size_t)l * DM, ln1_b + (size_t)l * DM);

        // ffn1 = relu(x16 @ f1w^T) -> g_f16 (f16)
        gemm_tc<<<dim3(DFF / 128, NN / 128), 256, GEMM_SMEM>>>(
            F16_X, F1W_OFF + l * F1W_PER, f1b, F16_F, 1, 1, NN, DM, DFF);

        // ffn2 = f16 @ f2w^T -> g_qkv (f32 scratch)
        gemm_tc<<<dim3(DM / 128, NN / 128), 256, GEMM_SMEM>>>(
            F16_F, F2W_OFF + l * F2W_PER, f2b, BUF_QKV, 0, 0, NN, DFF, DM);

        // h = LN(x + ffn2) -> g_h (f32) + g_h16
        ln_kernel<<<NN, 128>>>(BUF_X, BUF_QKV, BUF_H, F16_H,
                               ln2_g + (size_t)l * DM, ln2_b + (size_t)l * DM);
    }

    pool_kernel<<<BG, 256>>>();
    head_kernel<<<BG, 256>>>(head_w1, head_b1, head_w2, head_b2, out);
}

// round 15
// speedup vs baseline: 9.8989x; 1.4539x over previous
#include <cuda_runtime.h>
#include <cuda_fp16.h>
#include <math.h>
#include <stdint.h>

#define NN   24576
#define DIN  92
#define DM   512
#define NH   8
#define HD   64
#define NL   3
#define DFF  2048
#define BG   128
#define LN_EPS 1e-5f

// ---------------- scratch (static device globals; no allocs allowed) --------
__device__ float g_h[(size_t)NN * DM];          // f32 hidden (residual/pool)
__device__ float g_qkv[(size_t)NN * 3 * DM];    // f32 ffn2-out scratch
__device__ float g_x[(size_t)NN * DM];          // f32 post-LN1
__device__ float g_pooled[BG * DM];
__device__ int   g_counts[BG];
__device__ int   g_starts[BG];

__device__ __half g_h16[(size_t)NN * DM];       // f16 of hidden
__device__ __half g_x16[(size_t)NN * DM];       // f16 of post-LN1
__device__ __half g_t16[(size_t)NN * DM];       // f16 attn out
__device__ __half g_f16[(size_t)NN * DFF];      // f16 ffn hidden
__device__ __half g_qkv16[(size_t)NN * 3 * DM]; // f16 qkv
__device__ __half g_w16[9437184];               // f16 weights (all layers)

// f32 buffer ids
#define BUF_H    0
#define BUF_QKV  1
#define BUF_X    2
__device__ __forceinline__ float* buf_ptr(int id) {
    switch (id) {
        case BUF_H:   return g_h;
        case BUF_QKV: return g_qkv;
        default:      return g_x;
    }
}
// f16 buffer ids
#define F16_H    0
#define F16_X    1
#define F16_T    2
#define F16_F    3
#define F16_QKV  4
__device__ __forceinline__ __half* f16_ptr(int id) {
    switch (id) {
        case F16_H: return g_h16;
        case F16_X: return g_x16;
        case F16_T: return g_t16;
        case F16_F: return g_f16;
        default:    return g_qkv16;
    }
}

// weight offsets in g_w16 (halves)
#define IPW_OFF 0
#define IPW_PER (3 * DM * DM)
#define OW_OFF  (3 * IPW_PER)
#define OW_PER  (DM * DM)
#define F1W_OFF (OW_OFF + 3 * OW_PER)
#define F1W_PER (DFF * DM)
#define F2W_OFF (F1W_OFF + 3 * F1W_PER)
#define F2W_PER (DM * DFF)

// ---------------- PTX helpers ------------------------------------------------
__device__ __forceinline__ uint32_t smem_u32(const void* p) {
    uint32_t a;
    asm("{ .reg .u64 t; cvta.to.shared.u64 t, %1; cvt.u32.u64 %0, t; }"
        : "=r"(a) : "l"(p));
    return a;
}
#define CPA16(dst, src) \
    asm volatile("cp.async.ca.shared.global [%0], [%1], 16;" :: "r"(dst), "l"(src))
#define CPCOMMIT() asm volatile("cp.async.commit_group;" ::: "memory")
#define CPWAIT1()  asm volatile("cp.async.wait_group 1;" ::: "memory")
#define CPWAIT0()  asm volatile("cp.async.wait_group 0;" ::: "memory")
#define LDMX4(r0, r1, r2, r3, a) \
    asm volatile("ldmatrix.sync.aligned.m8n8.x4.shared.b16 {%0,%1,%2,%3}, [%4];" \
                 : "=r"(r0), "=r"(r1), "=r"(r2), "=r"(r3) : "r"(a))

__device__ __forceinline__ void mma_f16(float* c, const uint32_t* a,
                                        uint32_t b0, uint32_t b1) {
    asm volatile(
        "mma.sync.aligned.m16n8k16.row.col.f32.f16.f16.f32 "
        "{%0,%1,%2,%3}, {%4,%5,%6,%7}, {%8,%9}, {%0,%1,%2,%3};"
        : "+f"(c[0]), "+f"(c[1]), "+f"(c[2]), "+f"(c[3])
        : "r"(a[0]), "r"(a[1]), "r"(a[2]), "r"(a[3]), "r"(b0), "r"(b1));
}
__device__ __forceinline__ uint32_t pack_f16x2(float even, float odd) {
    uint32_t r;
    asm("cvt.rn.f16x2.f32 %0, %1, %2;" : "=r"(r) : "f"(odd), "f"(even));
    return r;
}

// ---------------- graph bookkeeping -----------------------------------------
__global__ __launch_bounds__(256) void k_bookkeep(const int* __restrict__ b32)
{
    __shared__ int s_cnt[BG];
    __shared__ int s_any;
    int tid = threadIdx.x;

    if (tid == 0) s_any = 0;
    for (int i = tid; i < BG; i += 256) s_cnt[i] = 0;
    __syncthreads();

    int any = 0;
    for (int i = (NN / 2) + 1 + 2 * tid; i < NN; i += 2 * 256)
        if (b32[i] != 0) any = 1;
    if (any) atomicOr(&s_any, 1);
    __syncthreads();
    int is64 = (s_any == 0);

    for (int i = tid; i < NN; i += 256) {
        int v = is64 ? b32[2 * i] : b32[i];
        v = min(max(v, 0), BG - 1);
        atomicAdd(&s_cnt[v], 1);
    }
    __syncthreads();

    if (tid == 0) {
        int s = 0;
        for (int i = 0; i < BG; i++) {
            g_counts[i] = s_cnt[i];
            g_starts[i] = s;
            s += s_cnt[i];
        }
    }
}

// ---------------- weight conversion fp32 -> fp16 -----------------------------
__device__ __forceinline__ void conv_region(
    const float* __restrict__ src, __half* __restrict__ dst, size_t n,
    size_t gid, size_t stride)
{
    __half2* d2 = (__half2*)dst;
    const float2* s2 = (const float2*)src;
    for (size_t i = gid; i < n / 2; i += stride)
        d2[i] = __floats2half2_rn(s2[i].x, s2[i].y);
}

__global__ __launch_bounds__(256) void k_wconvert(
    const float* __restrict__ ipw, const float* __restrict__ ow,
    const float* __restrict__ f1w, const float* __restrict__ f2w)
{
    size_t gid = (size_t)blockIdx.x * 256 + threadIdx.x;
    size_t stride = (size_t)gridDim.x * 256;
    conv_region(ipw, g_w16 + IPW_OFF, 3 * (size_t)IPW_PER, gid, stride);
    conv_region(ow,  g_w16 + OW_OFF,  3 * (size_t)OW_PER,  gid, stride);
    conv_region(f1w, g_w16 + F1W_OFF, 3 * (size_t)F1W_PER, gid, stride);
    conv_region(f2w, g_w16 + F2W_OFF, 3 * (size_t)F2W_PER, gid, stride);
}

// ---------------- fp16 tensor GEMM: C = A[M,K] @ W[N,K]^T + bias ------------
// 256x128 CTA tile, BK=32, 3-stage cp.async pipeline, ldmatrix fragments,
// 256 threads (8 warps as 4Mx2N), warp tile 64x64 (crossbar-optimal).
#define LDW 20                       // words per smem row (32 halves + pad)
#define ASTG_W (256 * LDW)           // A stage words
#define BSTG_W (128 * LDW)           // B stage words
#define ASTG_B (ASTG_W * 4)          // 20480 bytes
#define BSTG_B (BSTG_W * 4)          // 10240 bytes
#define NSTAGE 3
#define GEMM_SMEM (NSTAGE * (ASTG_B + BSTG_B))   // 92160

__global__ void __launch_bounds__(256, 1) gemm_tc(
    int aid, int woff, const float* __restrict__ bias,
    int cid, int out16, int act, int M, int K, int Nout)
{
    extern __shared__ uint32_t dsm[];
    const __half* A = f16_ptr(aid);
    const __half* W = g_w16 + woff;

    const int tid  = threadIdx.x;
    const int warp = tid >> 5;
    const int lane = tid & 31;
    const int g    = lane >> 2;
    const int tig  = lane & 3;
    const int wm   = (warp >> 1) * 64;   // 4 warps in M
    const int wn   = (warp & 1) * 64;    // 2 warps in N
    const int m0 = blockIdx.y * 256;
    const int n0 = blockIdx.x * 128;

    const uint32_t sbase = smem_u32(dsm);

    // loader: thread -> row (tid>>2) + 64*i, 16B chunk (tid&3)
    const int rowL = tid >> 2, chL = tid & 3;
    const __half* Aga = A + (size_t)(m0 + rowL) * K + chL * 8;
    const __half* Wga = W + (size_t)(n0 + rowL) * K + chL * 8;
    uint32_t sOff[4];
    #pragma unroll
    for (int i = 0; i < 4; i++)
        sOff[i] = ((rowL + 64 * i) * LDW + chL * 4) * 4;

    // ldmatrix per-lane offsets
    const int grp = lane >> 3, l8 = lane & 7;
    const int rsel = (grp & 1) * 8;
    const int kselB = (grp >> 1) * 16;   // bytes
    uint32_t aoff[4], boff[4];
    #pragma unroll
    for (int mb = 0; mb < 4; mb++)
        aoff[mb] = (wm + mb * 16 + rsel + l8) * 80 + kselB;
    #pragma unroll
    for (int nb = 0; nb < 4; nb++)
        boff[nb] = (wn + nb * 16 + rsel + l8) * 80 + kselB;

    float acc[4][8][4];
    #pragma unroll
    for (int i = 0; i < 4; i++)
        #pragma unroll
        for (int j = 0; j < 8; j++)
            #pragma unroll
            for (int r = 0; r < 4; r++) acc[i][j][r] = 0.f;

    const int S = K >> 5;

#define ISSUE(k0, st)                                               \
    do {                                                            \
        uint32_t ab = sbase + (st) * ASTG_B;                        \
        uint32_t wb = sbase + NSTAGE * ASTG_B + (st) * BSTG_B;      \
        CPA16(ab + sOff[0], Aga + (k0));                            \
        CPA16(ab + sOff[1], Aga + (k0) + (size_t)64 * K);           \
        CPA16(ab + sOff[2], Aga + (k0) + (size_t)128 * K);          \
        CPA16(ab + sOff[3], Aga + (k0) + (size_t)192 * K);          \
        CPA16(wb + sOff[0], Wga + (k0));                            \
        CPA16(wb + sOff[1], Wga + (k0) + (size_t)64 * K);           \
        CPCOMMIT();                                                 \
    } while (0)

#define COMPUTE(st)                                                          \
    do {                                                                     \
        uint32_t ab = sbase + (st) * ASTG_B;                                 \
        uint32_t wb = sbase + NSTAGE * ASTG_B + (st) * BSTG_B;               \
        _Pragma("unroll")                                                    \
        for (int ks = 0; ks < 2; ks++) {                                     \
            uint32_t kB = ks * 32;                                           \
            uint32_t af[4][4];                                               \
            _Pragma("unroll")                                                \
            for (int mb = 0; mb < 4; mb++)                                   \
                LDMX4(af[mb][0], af[mb][1], af[mb][2], af[mb][3],            \
                      ab + aoff[mb] + kB);                                   \
            _Pragma("unroll")                                                \
            for (int nb = 0; nb < 4; nb++) {                                 \
                uint32_t b0, b1, b2, b3;                                     \
                LDMX4(b0, b1, b2, b3, wb + boff[nb] + kB);                   \
                _Pragma("unroll")                                            \
                for (int mb = 0; mb < 4; mb++) {                             \
                    mma_f16(acc[mb][2 * nb],     af[mb], b0, b2);            \
                    mma_f16(acc[mb][2 * nb + 1], af[mb], b1, b3);            \
                }                                                            \
            }                                                                \
        }                                                                    \
    } while (0)

    ISSUE(0, 0);
    ISSUE(32, 1);
    for (int s = 0; s < S; s++) {
        if (s == S - 1) CPWAIT0(); else CPWAIT1();
        __syncthreads();
        if (s + 2 < S) ISSUE((s + 2) * 32, (s + 2) % NSTAGE);
        COMPUTE(s % NSTAGE);
    }
#undef ISSUE
#undef COMPUTE

    // epilogue
    if (out16) {
        __half* C = f16_ptr(cid);
        #pragma unroll
        for (int j = 0; j < 8; j++) {
            int col = n0 + wn + j * 8 + 2 * tig;
            float2 bv = *(const float2*)(bias + col);
            #pragma unroll
            for (int mb = 0; mb < 4; mb++) {
                int row0 = m0 + wm + mb * 16 + g;
                float v0 = acc[mb][j][0] + bv.x;
                float v1 = acc[mb][j][1] + bv.y;
                float v2 = acc[mb][j][2] + bv.x;
                float v3 = acc[mb][j][3] + bv.y;
                if (act) {
                    v0 = fmaxf(v0, 0.f); v1 = fmaxf(v1, 0.f);
                    v2 = fmaxf(v2, 0.f); v3 = fmaxf(v3, 0.f);
                }
                *(uint32_t*)(C + (size_t)row0 * Nout + col)       = pack_f16x2(v0, v1);
                *(uint32_t*)(C + (size_t)(row0 + 8) * Nout + col) = pack_f16x2(v2, v3);
            }
        }
    } else {
        float* C = buf_ptr(cid);
        #pragma unroll
        for (int j = 0; j < 8; j++) {
            int col = n0 + wn + j * 8 + 2 * tig;
            float2 bv = *(const float2*)(bias + col);
            #pragma unroll
            for (int mb = 0; mb < 4; mb++) {
                int row0 = m0 + wm + mb * 16 + g;
                float v0 = acc[mb][j][0] + bv.x;
                float v1 = acc[mb][j][1] + bv.y;
                float v2 = acc[mb][j][2] + bv.x;
                float v3 = acc[mb][j][3] + bv.y;
                if (act) {
                    v0 = fmaxf(v0, 0.f); v1 = fmaxf(v1, 0.f);
                    v2 = fmaxf(v2, 0.f); v3 = fmaxf(v3, 0.f);
                }
                *(float2*)(C + (size_t)row0 * Nout + col)       = make_float2(v0, v1);
                *(float2*)(C + (size_t)(row0 + 8) * Nout + col) = make_float2(v2, v3);
            }
        }
    }
}

// ---------------- fp32 SIMT GEMM (embedding: K=92) + f16 copy ---------------
__global__ __launch_bounds__(256) void gemm_f32(
    const float* __restrict__ Aext,
    const float* __restrict__ W, const float* __restrict__ bias,
    int M, int K, int Nout)
{
    __shared__ __align__(16) float As[2][16][132];
    __shared__ __align__(16) float Ws[2][16][132];

    const float* A = Aext;

    const int tid = threadIdx.x;
    const int tx = tid & 15;
    const int ty = tid >> 4;
    const int m0 = blockIdx.y * 128;
    const int n0 = blockIdx.x * 128;

    const int lr = tid >> 2;
    const int lc = (tid & 3) * 4;

    const float* Ap0 = A + (size_t)(m0 + lr) * K;
    const float* Ap1 = A + (size_t)(m0 + lr + 64) * K;
    const float* Wp0 = W + (size_t)(n0 + lr) * K;
    const float* Wp1 = W + (size_t)(n0 + lr + 64) * K;

    float acc[8][8];
    #pragma unroll
    for (int i = 0; i < 8; i++)
        #pragma unroll
        for (int j = 0; j < 8; j++) acc[i][j] = 0.f;

    float4 ra0, ra1, rw0, rw1;
    const int ktiles = (K + 15) >> 4;

#define GLOAD(k0)                                                            \
    do {                                                                     \
        float* p0 = (float*)&ra0; float* p1 = (float*)&ra1;                  \
        float* q0 = (float*)&rw0; float* q1 = (float*)&rw1;                  \
        _Pragma("unroll")                                                    \
        for (int i = 0; i < 4; i++) {                                        \
            int kg = (k0) + lc + i;                                          \
            bool ok = (kg < K);                                              \
            p0[i] = ok ? Ap0[kg] : 0.f;                                      \
            p1[i] = ok ? Ap1[kg] : 0.f;                                      \
            q0[i] = ok ? Wp0[kg] : 0.f;                                      \
            q1[i] = ok ? Wp1[kg] : 0.f;                                      \
        }                                                                    \
    } while (0)

#define SSTORE(bf)                                                           \
    do {                                                                     \
        As[bf][lc + 0][lr]      = ra0.x; As[bf][lc + 1][lr]      = ra0.y;    \
        As[bf][lc + 2][lr]      = ra0.z; As[bf][lc + 3][lr]      = ra0.w;    \
        As[bf][lc + 0][lr + 64] = ra1.x; As[bf][lc + 1][lr + 64] = ra1.y;    \
        As[bf][lc + 2][lr + 64] = ra1.z; As[bf][lc + 3][lr + 64] = ra1.w;    \
        Ws[bf][lc + 0][lr]      = rw0.x; Ws[bf][lc + 1][lr]      = rw0.y;    \
        Ws[bf][lc + 2][lr]      = rw0.z; Ws[bf][lc + 3][lr]      = rw0.w;    \
        Ws[bf][lc + 0][lr + 64] = rw1.x; Ws[bf][lc + 1][lr + 64] = rw1.y;    \
        Ws[bf][lc + 2][lr + 64] = rw1.z; Ws[bf][lc + 3][lr + 64] = rw1.w;    \
    } while (0)

#define COMPUTE(bf)                                                          \
    do {                                                                     \
        _Pragma("unroll")                                                    \
        for (int k = 0; k < 16; k++) {                                       \
            float4 a0 = *(const float4*)(&As[bf][k][ty * 8]);                \
            float4 a1 = *(const float4*)(&As[bf][k][ty * 8 + 4]);            \
            float4 b0 = *(const float4*)(&Ws[bf][k][tx * 8]);                \
            float4 b1 = *(const float4*)(&Ws[bf][k][tx * 8 + 4]);            \
            float ar[8] = {a0.x, a0.y, a0.z, a0.w, a1.x, a1.y, a1.z, a1.w};  \
            float br[8] = {b0.x, b0.y, b0.z, b0.w, b1.x, b1.y, b1.z, b1.w};  \
            _Pragma("unroll")                                                \
            for (int i = 0; i < 8; i++)                                      \
                _Pragma("unroll")                                            \
                for (int j = 0; j < 8; j++)                                  \
                    acc[i][j] = fmaf(ar[i], br[j], acc[i][j]);               \
        }                                                                    \
    } while (0)

    GLOAD(0);
    SSTORE(0);
    __syncthreads();

    for (int kt = 0; kt < ktiles; kt++) {
        int bf = kt & 1;
        if (kt + 1 < ktiles) GLOAD((kt + 1) * 16);
        COMPUTE(bf);
        if (kt + 1 < ktiles) {
            SSTORE(bf ^ 1);
            __syncthreads();
        }
    }
#undef GLOAD
#undef SSTORE
#undef COMPUTE

    float4 bia0 = *(const float4*)(bias + n0 + tx * 8);
    float4 bia1 = *(const float4*)(bias + n0 + tx * 8 + 4);
    float bb[8] = {bia0.x, bia0.y, bia0.z, bia0.w, bia1.x, bia1.y, bia1.z, bia1.w};

    #pragma unroll
    for (int i = 0; i < 8; i++) {
        int m = m0 + ty * 8 + i;
        float*  Crow = g_h   + (size_t)m * Nout + n0 + tx * 8;
        __half* Hrow = g_h16 + (size_t)m * Nout + n0 + tx * 8;
        float r[8];
        #pragma unroll
        for (int j = 0; j < 8; j++) r[j] = acc[i][j] + bb[j];
        *(float4*)(Crow)     = make_float4(r[0], r[1], r[2], r[3]);
        *(float4*)(Crow + 4) = make_float4(r[4], r[5], r[6], r[7]);
        #pragma unroll
        for (int j = 0; j < 4; j++)
            *(uint32_t*)(Hrow + 2 * j) = pack_f16x2(r[2 * j], r[2 * j + 1]);
    }
}

// ---------------- tensor-core ragged flash attention -------------------------
// 128 threads (4 warps), grid (BG, NH, 16 q-tiles of 32).
__global__ __launch_bounds__(128) void attn_kernel()
{
    int b  = blockIdx.x;
    int h  = blockIdx.y;
    int qt = blockIdx.z;
    int cnt = g_counts[b];
    int q0  = qt * 32;
    if (q0 >= cnt) return;
    int start = g_starts[b];
    int nq = min(32, cnt - q0);

    __shared__ __half Qs[32][72];
    __shared__ __half Ks[32][72];
    __shared__ __half Vs[64][40];
    __shared__ __half Ps[32][40];
    __shared__ float  Sc[32][34];
    __shared__ float  s_m[32], s_l[32], s_corr[32];

    const int tid  = threadIdx.x;
    const int warp = tid >> 5;
    const int lane = tid & 31;
    const int grp = lane >> 3, l8 = lane & 7;
    const int rsel = (grp & 1) * 8;
    const int ksel16 = (grp >> 1) * 16;
    const int qr = lane >> 2;
    const int qc = lane & 3;

    const uint32_t qb = smem_u32(&Qs[0][0]);
    const uint32_t kb = smem_u32(&Ks[0][0]);
    const uint32_t vb = smem_u32(&Vs[0][0]);
    const uint32_t pb = smem_u32(&Ps[0][0]);

    {
        const __half* Qg = g_qkv16 + (size_t)(start + q0) * (3 * DM) + h * HD;
        #pragma unroll
        for (int c = tid; c < 256; c += 128) {
            int r = c >> 3, off = (c & 7) * 8;
            uint4 v = make_uint4(0, 0, 0, 0);
            if (r < nq) v = *(const uint4*)(Qg + (size_t)r * (3 * DM) + off);
            *(uint4*)(&Qs[r][off]) = v;
        }
    }
    if (tid < 32) { s_m[tid] = -INFINITY; s_l[tid] = 0.f; }

    float accO[2][2][4];
    #pragma unroll
    for (int i = 0; i < 2; i++)
        #pragma unroll
        for (int j = 0; j < 2; j++)
            #pragma unroll
            for (int r = 0; r < 4; r++) accO[i][j][r] = 0.f;

    const int mi = warp >> 1;
    const int nj = warp & 1;
    const float scale = 0.125f;

    int ktiles = (cnt + 31) >> 5;
    for (int kt = 0; kt < ktiles; kt++) {
        int k0 = kt * 32;
        int nk = min(32, cnt - k0);
        __syncthreads();

        const __half* Kg = g_qkv16 + (size_t)(start + k0) * (3 * DM) + DM + h * HD;
        #pragma unroll
        for (int c = tid; c < 256; c += 128) {
            int r = c >> 3, off = (c & 7) * 8;
            if (r < nk)
                *(uint4*)(&Ks[r][off]) = *(const uint4*)(Kg + (size_t)r * (3 * DM) + off);
        }
        {
            const __half* Vg = g_qkv16 + (size_t)(start + k0) * (3 * DM) + 2 * DM + h * HD;
            int r = lane, dc = warp * 16;
            if (r < nk) {
                const __half* src = Vg + (size_t)r * (3 * DM) + dc;
                #pragma unroll
                for (int i = 0; i < 16; i++) Vs[dc + i][r] = src[i];
            } else {
                #pragma unroll
                for (int i = 0; i < 16; i++) Vs[dc + i][r] = __ushort_as_half(0);
            }
        }
        __syncthreads();

        float accS[2][4] = {{0.f, 0.f, 0.f, 0.f}, {0.f, 0.f, 0.f, 0.f}};
        #pragma unroll
        for (int kc = 0; kc < 4; kc++) {
            uint32_t a0, a1, a2, a3, b0, b1, b2, b3;
            LDMX4(a0, a1, a2, a3,
                  qb + (mi * 16 + rsel + l8) * 144 + kc * 32 + ksel16);
            LDMX4(b0, b1, b2, b3,
                  kb + (nj * 16 + rsel + l8) * 144 + kc * 32 + ksel16);
            uint32_t af[4] = {a0, a1, a2, a3};
            mma_f16(accS[0], af, b0, b2);
            mma_f16(accS[1], af, b1, b3);
        }
        {
            int r0 = mi * 16 + qr;
            #pragma unroll
            for (int jn = 0; jn < 2; jn++) {
                int c0 = nj * 16 + jn * 8 + 2 * qc;
                Sc[r0][c0]         = accS[jn][0] * scale;
                Sc[r0][c0 + 1]     = accS[jn][1] * scale;
                Sc[r0 + 8][c0]     = accS[jn][2] * scale;
                Sc[r0 + 8][c0 + 1] = accS[jn][3] * scale;
            }
        }
        __syncthreads();

        {
            int q = tid >> 2, s4 = tid & 3;
            float v[8];
            float mx = -INFINITY;
            #pragma unroll
            for (int i = 0; i < 8; i++) {
                int k = s4 * 8 + i;
                v[i] = (k < nk) ? Sc[q][k] : -INFINITY;
                mx = fmaxf(mx, v[i]);
            }
            mx = fmaxf(mx, __shfl_xor_sync(0xffffffffu, mx, 1));
            mx = fmaxf(mx, __shfl_xor_sync(0xffffffffu, mx, 2));
            float mold = s_m[q];
            float mnew = fmaxf(mold, mx);
            float sum = 0.f;
            float p[8];
            #pragma unroll
            for (int i = 0; i < 8; i++) {
                p[i] = __expf(v[i] - mnew);
                sum += p[i];
            }
            sum += __shfl_xor_sync(0xffffffffu, sum, 1);
            sum += __shfl_xor_sync(0xffffffffu, sum, 2);
            #pragma unroll
            for (int i = 0; i < 4; i++)
                *(uint32_t*)(&Ps[q][s4 * 8 + 2 * i]) = pack_f16x2(p[2 * i], p[2 * i + 1]);
            if (s4 == 0) {
                float corr = __expf(mold - mnew);
                s_m[q] = mnew;
                s_l[q] = s_l[q] * corr + sum;
                s_corr[q] = corr;
            }
        }
        __syncthreads();

        {
            #pragma unroll
            for (int m2 = 0; m2 < 2; m2++) {
                float c0 = s_corr[m2 * 16 + qr];
                float c1 = s_corr[m2 * 16 + qr + 8];
                #pragma unroll
                for (int jn = 0; jn < 2; jn++) {
                    accO[m2][jn][0] *= c0; accO[m2][jn][1] *= c0;
                    accO[m2][jn][2] *= c1; accO[m2][jn][3] *= c1;
                }
            }
            #pragma unroll
            for (int kc = 0; kc < 2; kc++) {
                uint32_t b0, b1, b2, b3;
                LDMX4(b0, b1, b2, b3,
                      vb + (warp * 16 + rsel + l8) * 80 + kc * 32 + ksel16);
                #pragma unroll
                for (int m2 = 0; m2 < 2; m2++) {
                    uint32_t a0, a1, a2, a3;
                    LDMX4(a0, a1, a2, a3,
                          pb + (m2 * 16 + rsel + l8) * 80 + kc * 32 + ksel16);
                    uint32_t af[4] = {a0, a1, a2, a3};
                    mma_f16(accO[m2][0], af, b0, b2);
                    mma_f16(accO[m2][1], af, b1, b3);
                }
            }
        }
    }

    #pragma unroll
    for (int m2 = 0; m2 < 2; m2++) {
        int r = m2 * 16 + qr;
        int r2 = r + 8;
        float inv  = (r  < nq) ? 1.f / s_l[r]  : 0.f;
        float inv2 = (r2 < nq) ? 1.f / s_l[r2] : 0.f;
        #pragma unroll
        for (int jn = 0; jn < 2; jn++) {
            int col = h * HD + warp * 16 + jn * 8 + 2 * qc;
            if (r < nq)
                *(uint32_t*)(g_t16 + (size_t)(start + q0 + r) * DM + col) =
                    pack_f16x2(accO[m2][jn][0] * inv, accO[m2][jn][1] * inv);
            if (r2 < nq)
                *(uint32_t*)(g_t16 + (size_t)(start + q0 + r2) * DM + col) =
                    pack_f16x2(accO[m2][jn][2] * inv2, accO[m2][jn][3] * inv2);
        }
    }
}

// ---------------- residual + layernorm (f32 out + f16 out) -------------------
__global__ __launch_bounds__(128) void ln_kernel(
    int rid, int did, int oid, int oid16,
    const float* __restrict__ gg, const float* __restrict__ bb)
{
    const float* resid = buf_ptr(rid);
    const float* delta = buf_ptr(did);
    float*       out   = buf_ptr(oid);
    __half*      out16 = f16_ptr(oid16);

    int row = blockIdx.x;
    int tid = threadIdx.x;
    size_t base = (size_t)row * DM;

    float v[4];
    float s = 0.f, sq = 0.f;
    #pragma unroll
    for (int i = 0; i < 4; i++) {
        int c = tid + i * 128;
        float x = resid[base + c] + delta[base + c];
        v[i] = x;
        s += x; sq += x * x;
    }
    __shared__ float shs[4], shq[4];
    #pragma unroll
    for (int o = 16; o > 0; o >>= 1) {
        s  += __shfl_down_sync(0xffffffffu, s, o);
        sq += __shfl_down_sync(0xffffffffu, sq, o);
    }
    int w = tid >> 5;
    if ((tid & 31) == 0) { shs[w] = s; shq[w] = sq; }
    __syncthreads();
    float ts = shs[0] + shs[1] + shs[2] + shs[3];
    float tq = shq[0] + shq[1] + shq[2] + shq[3];
    float mean = ts * (1.f / DM);
    float var  = tq * (1.f / DM) - mean * mean;
    float inv  = rsqrtf(fmaxf(var, 0.f) + LN_EPS);
    #pragma unroll
    for (int i = 0; i < 4; i++) {
        int c = tid + i * 128;
        float r = (v[i] - mean) * inv * gg[c] + bb[c];
        out[base + c] = r;
        out16[base + c] = __float2half(r);
    }
}

// ---------------- segment mean pool -----------------------------------------
__global__ __launch_bounds__(256) void pool_kernel()
{
    int b = blockIdx.x;
    int tid = threadIdx.x;
    int cnt = g_counts[b], st = g_starts[b];
    float a0 = 0.f, a1 = 0.f;
    for (int r = 0; r < cnt; r++) {
        size_t base = (size_t)(st + r) * DM;
        a0 += g_h[base + tid];
        a1 += g_h[base + tid + 256];
    }
    float inv = (cnt > 0) ? 1.f / (float)cnt : 0.f;
    g_pooled[b * DM + tid]       = a0 * inv;
    g_pooled[b * DM + tid + 256] = a1 * inv;
}

// ---------------- head ------------------------------------------------------
__global__ __launch_bounds__(256) void head_kernel(
    const float* __restrict__ w1, const float* __restrict__ b1,
    const float* __restrict__ w2, const float* __restrict__ b2,
    float* __restrict__ out)
{
    int b = blockIdx.x;
    int tid = threadIdx.x;
    __shared__ float ps[DM];
    ps[tid]       = g_pooled[b * DM + tid];
    ps[tid + 256] = g_pooled[b * DM + tid + 256];
    __syncthreads();

    int warp = tid >> 5, lane = tid & 31;
    float partial = 0.f;
    for (int j = warp; j < DM; j += 8) {
        float a = 0.f;
        const float* wr = w1 + (size_t)j * DM;
        for (int k = lane; k < DM; k += 32) a = fmaf(ps[k], wr[k], a);
        #pragma unroll
        for (int o = 16; o > 0; o >>= 1) a += __shfl_down_sync(0xffffffffu, a, o);
        if (lane == 0) {
            a += b1[j];
            float sil = a / (1.f + __expf(-a));
            partial = fmaf(sil, w2[j], partial);
        }
    }
    __shared__ float red[8];
    if (lane == 0) red[warp] = partial;
    __syncthreads();
    if (tid == 0) {
        float t = 0.f;
        #pragma unroll
        for (int i = 0; i < 8; i++) t += red[i];
        out[b] = t + b2[0];
    }
}

// ---------------- launch -----------------------------------------------------
extern "C" void kernel_launch(void* const* d_in, const int* in_sizes, int n_in,
                              void* d_out, int out_size)
{
    const float* node_features = (const float*)d_in[0];
    const int*   batch32       = (const int*)d_in[3];
    const float* emb_w    = (const float*)d_in[4];
    const float* emb_b    = (const float*)d_in[5];
    const float* in_proj_w = (const float*)d_in[6];
    const float* in_proj_b = (const float*)d_in[7];
    const float* out_w    = (const float*)d_in[8];
    const float* out_b    = (const float*)d_in[9];
    const float* ln1_g    = (const float*)d_in[10];
    const float* ln1_b    = (const float*)d_in[11];
    const float* ffn_w1   = (const float*)d_in[12];
    const float* ffn_b1   = (const float*)d_in[13];
    const float* ffn_w2   = (const float*)d_in[14];
    const float* ffn_b2   = (const float*)d_in[15];
    const float* ln2_g    = (const float*)d_in[16];
    const float* ln2_b    = (const float*)d_in[17];
    const float* head_w1  = (const float*)d_in[18];
    const float* head_b1  = (const float*)d_in[19];
    const float* head_w2  = (const float*)d_in[20];
    const float* head_b2  = (const float*)d_in[21];
    float* out = (float*)d_out;

    cudaFuncSetAttribute(gemm_tc, cudaFuncAttributeMaxDynamicSharedMemorySize,
                         GEMM_SMEM);

    k_bookkeep<<<1, 256>>>(batch32);
    k_wconvert<<<2048, 256>>>(in_proj_w, out_w, ffn_w1, ffn_w2);

    // embedding (fp32, K=92) -> g_h + g_h16
    gemm_f32<<<dim3(DM / 128, NN / 128), 256>>>(
        node_features, emb_w, emb_b, NN, DIN, DM);

    for (int l = 0; l < NL; l++) {
        const float* ipb = in_proj_b + (size_t)l * 3 * DM;
        const float* ob  = out_b + (size_t)l * DM;
        const float* f1b = ffn_b1 + (size_t)l * DFF;
        const float* f2b = ffn_b2 + (size_t)l * DM;

        // qkv = h16 @ ipw^T -> g_qkv16 (f16)
        gemm_tc<<<dim3(3 * DM / 128, NN / 256), 256, GEMM_SMEM>>>(
            F16_H, IPW_OFF + l * IPW_PER, ipb, F16_QKV, 1, 0, NN, DM, 3 * DM);

        // tensor-core attention -> g_t16
        attn_kernel<<<dim3(BG, NH, 16), 128>>>();

        // o proj = t16 @ ow^T -> g_x (f32)
        gemm_tc<<<dim3(DM / 128, NN / 256), 256, GEMM_SMEM>>>(
            F16_T, OW_OFF + l * OW_PER, ob, BUF_X, 0, 0, NN, DM, DM);

        // x = LN(h + o) -> g_x (f32) + g_x16
        ln_kernel<<<NN, 128>>>(BUF_H, BUF_X, BUF_X, F16_X,
                               ln1_g + (size_t)l * DM, ln1_b + (size_t)l * DM);

        // ffn1 = relu(x16 @ f1w^T) -> g_f16 (f16)
        gemm_tc<<<dim3(DFF / 128, NN / 256), 256, GEMM_SMEM>>>(
            F16_X, F1W_OFF + l * F1W_PER, f1b, F16_F, 1, 1, NN, DM, DFF);

        // ffn2 = f16 @ f2w^T -> g_qkv (f32 scratch)
        gemm_tc<<<dim3(DM / 128, NN / 256), 256, GEMM_SMEM>>>(
            F16_F, F2W_OFF + l * F2W_PER, f2b, BUF_QKV, 0, 0, NN, DFF, DM);

        // h = LN(x + ffn2) -> g_h (f32) + g_h16
        ln_kernel<<<NN, 128>>>(BUF_X, BUF_QKV, BUF_H, F16_H,
                               ln2_g + (size_t)l * DM, ln2_b + (size_t)l * DM);
    }

    pool_kernel<<<BG, 256>>>();
    head_kernel<<<BG, 256>>>(head_w1, head_b1, head_w2, head_b2, out);
}